// round 12
// baseline (speedup 1.0000x reference)
#include <cuda_runtime.h>
#include <cuda_bf16.h>
#include <cuda_fp16.h>
#include <cstdint>

#define NN 50000
#define MAXE 1600000
#define KPADMAX 1536

// ---------------- scratch (static device globals) ---------------------------
__device__ __align__(16) float g_tx1[NN * 512];
__device__ __align__(16) float g_tx2[NN * 512];
__device__ __align__(16) float g_h1 [NN * 256];   // stride 256, 250 valid
__device__ __align__(16) float g_h2 [NN * 500];   // stride 500
__device__ __align__(16) float g_u  [NN * 768];   // layer-1 GEMM out [u0|u1|u2]
__device__ __align__(16) __half g_f16a[(size_t)NN * 768];  // mirror A
__device__ __align__(16) __half g_f16b[(size_t)NN * 512];  // mirror B
__device__ __align__(16) __nv_bfloat16 g_Ahi[(size_t)NN * KPADMAX];
__device__ __align__(16) __nv_bfloat16 g_Alo[(size_t)NN * KPADMAX];
__device__ __align__(16) __nv_bfloat16 g_Wthi[1024 * KPADMAX];
__device__ __align__(16) __nv_bfloat16 g_Wtlo[1024 * KPADMAX];
__device__ int   g_deg[NN];
__device__ int   g_rowptr[NN + 1];
__device__ int   g_cursor[NN];
__device__ int   g_colidx[MAXE];
__device__ float g_dis[NN];
__device__ float g_diag[NN];
__device__ int   g_is64;

__device__ __forceinline__ const float* selbuf(int sel, const float* ext) {
    switch (sel) {
        case 1: return g_tx1;
        case 2: return g_tx2;
        case 3: return g_h1;
        case 4: return g_h2;
        case 5: return g_u;
        default: return ext;
    }
}
__device__ __forceinline__ float* selbuf_mut(int sel, float* ext) {
    switch (sel) {
        case 1: return g_tx1;
        case 2: return g_tx2;
        case 3: return g_h1;
        case 4: return g_h2;
        case 5: return g_u;
        default: return ext;
    }
}
__device__ __forceinline__ __half* selh(int sel) {
    switch (sel) {
        case 6: return g_f16a;
        case 7: return g_f16b;
        default: return nullptr;
    }
}

__device__ __forceinline__ int edge_at(const void* ei, int E, long long idx) {
    if (g_is64) return (int)((const long long*)ei)[idx];
    return ((const int*)ei)[idx];
}

__device__ __forceinline__ uint32_t smem_to_u32(const void* p) {
    uint32_t a;
    asm("{ .reg .u64 t; cvta.to.shared.u64 t, %1; cvt.u32.u64 %0, t; }"
        : "=r"(a) : "l"(p));
    return a;
}

// mma.sync bf16 (sm_80 path; legal on plain sm_103 target)
__device__ __forceinline__ void mma_bf16(float* c, const uint32_t* a, const uint32_t* b) {
    asm volatile("mma.sync.aligned.m16n8k16.row.col.f32.bf16.bf16.f32 "
        "{%0,%1,%2,%3}, {%4,%5,%6,%7}, {%8,%9}, {%0,%1,%2,%3};"
        : "+f"(c[0]), "+f"(c[1]), "+f"(c[2]), "+f"(c[3])
        : "r"(a[0]), "r"(a[1]), "r"(a[2]), "r"(a[3]), "r"(b[0]), "r"(b[1]));
}
__device__ __forceinline__ void ldsm4(uint32_t* r, uint32_t addr) {
    asm volatile("ldmatrix.sync.aligned.m8n8.x4.shared.b16 {%0,%1,%2,%3}, [%4];"
        : "=r"(r[0]), "=r"(r[1]), "=r"(r[2]), "=r"(r[3]) : "r"(addr));
}
__device__ __forceinline__ void cp16(uint32_t dst, const void* src, int src_bytes) {
    asm volatile("cp.async.cg.shared.global [%0], [%1], 16, %2;"
                 :: "r"(dst), "l"(src), "r"(src_bytes));
}
#define CP_COMMIT() asm volatile("cp.async.commit_group;" ::: "memory")
#define CP_WAIT2()  asm volatile("cp.async.wait_group 2;" ::: "memory")
#define CP_WAIT1()  asm volatile("cp.async.wait_group 1;" ::: "memory")
#define CP_WAIT0()  asm volatile("cp.async.wait_group 0;" ::: "memory")

// ---------------- dtype detection -------------------------------------------
__global__ void k_detect(const int* __restrict__ ei32) {
    if (threadIdx.x == 0 && blockIdx.x == 0) {
        int all0 = 1;
        for (int i = 0; i < 64; i++)
            if (ei32[2 * i + 1] != 0) { all0 = 0; break; }
        g_is64 = all0;
    }
}

// ---------------- graph preprocessing ---------------------------------------
__global__ void k_zero_deg() {
    int i = blockIdx.x * blockDim.x + threadIdx.x;
    if (i < NN) g_deg[i] = 0;
}
__global__ void k_count(const void* __restrict__ ei, int E) {
    int e = blockIdx.x * blockDim.x + threadIdx.x;
    if (e < E) {
        int dst = edge_at(ei, E, (long long)E + e);
        if ((unsigned)dst < NN) atomicAdd(&g_deg[dst], 1);
    }
}
__global__ void k_dis() {
    int i = blockIdx.x * blockDim.x + threadIdx.x;
    if (i < NN) {
        int d = g_deg[i];
        g_dis[i]  = d > 0 ? rsqrtf((float)d) : 0.0f;
        g_diag[i] = d > 0 ? 0.0f : -1.0f;
    }
}
__global__ void k_scan() {
    __shared__ int sm[1024];
    __shared__ int carry;
    if (threadIdx.x == 0) { carry = 0; g_rowptr[0] = 0; }
    __syncthreads();
    for (int base = 0; base < NN; base += 1024) {
        int i = base + threadIdx.x;
        int v = (i < NN) ? g_deg[i] : 0;
        sm[threadIdx.x] = v;
        __syncthreads();
        for (int off = 1; off < 1024; off <<= 1) {
            int t = (threadIdx.x >= off) ? sm[threadIdx.x - off] : 0;
            __syncthreads();
            sm[threadIdx.x] += t;
            __syncthreads();
        }
        if (i < NN) g_rowptr[i + 1] = carry + sm[threadIdx.x];
        __syncthreads();
        if (threadIdx.x == 0) carry += sm[1023];
        __syncthreads();
    }
}
__global__ void k_cursor() {
    int i = blockIdx.x * blockDim.x + threadIdx.x;
    if (i < NN) g_cursor[i] = g_rowptr[i];
}
__global__ void k_fill(const void* __restrict__ ei, int E) {
    int e = blockIdx.x * blockDim.x + threadIdx.x;
    if (e < E) {
        int dst = edge_at(ei, E, (long long)E + e);
        int src = edge_at(ei, E, e);
        if ((unsigned)dst < NN && (unsigned)src < NN) {
            int pos = atomicAdd(&g_cursor[dst], 1);
            if ((unsigned)pos < MAXE) g_colidx[pos] = src;
        }
    }
}

// ---------------- SpMM with fp16 gather (warp per dst row, CSR) -------------
// out = mul*(diag[row]*hrow[row] - dis[row]*sum(dis[s]*g16[s])) +
//       subcoef*sub[row] (+bias, relu). Optional fp16 mirror of out.
template <int F>
__global__ void k_spmmh(
    int gsel, int goff, int gstr,                       // fp16 gather source
    const float* __restrict__ ext, int rsel, int roff, int rstr,  // fp32 row-local
    int ssel, int soff, int sstr,                       // fp32 sub term
    int osel, int ostr,                                 // fp32 out
    float mul, float subcoef,
    const float* __restrict__ bias, int do_relu,
    int msel, int mstr) {                               // fp16 mirror out
    constexpr int NC = (F + 3) / 4;          // chunks of 4 halves
    constexpr int NR = (NC + 31) / 32;
    const __half* g = selh(gsel) + goff;
    const float* hrow = selbuf(rsel, ext) + roff;
    const float* hsub = selbuf(ssel, ext) + soff;
    float* out = selbuf_mut(osel, nullptr);
    __half* mir = selh(msel);

    int warp = (blockIdx.x * blockDim.x + threadIdx.x) >> 5;
    int lane = threadIdx.x & 31;
    if (warp >= NN) return;
    int row = warp;
    int s = g_rowptr[row], e = g_rowptr[row + 1];

    float4 acc[NR];
#pragma unroll
    for (int r = 0; r < NR; r++) acc[r] = make_float4(0.f, 0.f, 0.f, 0.f);

    for (int j = s; j < e; j++) {
        int src = g_colidx[j];
        float ws = g_dis[src];
        const uint2* gp = (const uint2*)(g + (size_t)src * gstr);
#pragma unroll
        for (int r = 0; r < NR; r++) {
            int c = lane + r * 32;
            if ((NC & 31) == 0 || c < NC) {
                uint2 v = gp[c];
                float2 f0 = __half22float2(*(const __half2*)&v.x);
                float2 f1 = __half22float2(*(const __half2*)&v.y);
                acc[r].x += ws * f0.x; acc[r].y += ws * f0.y;
                acc[r].z += ws * f1.x; acc[r].w += ws * f1.y;
            }
        }
    }

    float di = g_dis[row], dg = g_diag[row];
    const float* hr = hrow + (size_t)row * rstr;
    const float* sr = hsub + (size_t)row * sstr;
    float* orow = out + (size_t)row * ostr;
    __half* mrow = mir ? (mir + (size_t)row * mstr) : nullptr;

#pragma unroll
    for (int r = 0; r < NR; r++) {
        int c = lane + r * 32;
        if ((NC & 31) != 0 && c >= NC) continue;
        int base = 4 * c;
        float a[4] = {acc[r].x, acc[r].y, acc[r].z, acc[r].w};
        if (base + 4 <= F) {
            float4 h = *(const float4*)(hr + base);
            float v[4];
            v[0] = mul * (dg * h.x - di * a[0]);
            v[1] = mul * (dg * h.y - di * a[1]);
            v[2] = mul * (dg * h.z - di * a[2]);
            v[3] = mul * (dg * h.w - di * a[3]);
            if (subcoef != 0.0f) {
                float4 sv = *(const float4*)(sr + base);
                v[0] += subcoef * sv.x; v[1] += subcoef * sv.y;
                v[2] += subcoef * sv.z; v[3] += subcoef * sv.w;
            }
            if (bias) {
                float4 bv = *(const float4*)(bias + base);
                v[0] += bv.x; v[1] += bv.y; v[2] += bv.z; v[3] += bv.w;
            }
            if (do_relu) {
#pragma unroll
                for (int q = 0; q < 4; q++) v[q] = v[q] > 0.f ? v[q] : 0.f;
            }
            *(float4*)(orow + base) = make_float4(v[0], v[1], v[2], v[3]);
            if (mrow) {
                uint2 mv;
                __half2 p0 = __floats2half2_rn(v[0], v[1]);
                __half2 p1 = __floats2half2_rn(v[2], v[3]);
                mv.x = *(const uint32_t*)&p0;
                mv.y = *(const uint32_t*)&p1;
                *(uint2*)(mrow + base) = mv;
            }
        } else {
#pragma unroll
            for (int q = 0; q < 4; q++) {
                int idx = base + q;
                if (idx < F) {
                    float v = mul * (dg * hr[idx] - di * a[q]);
                    if (subcoef != 0.0f) v += subcoef * sr[idx];
                    if (bias) v += bias[idx];
                    if (do_relu) v = v > 0.f ? v : 0.f;
                    orow[idx] = v;
                    if (mrow) mrow[idx] = __float2half_rn(v);
                }
            }
        }
    }
}

// ---------------- bf16 hi/lo conversion kernels ------------------------------
// A = [A0|A1(tx1)|A2(tx2)] fp32 -> hi/lo [NN,Kpad]; zero-padded beyond 3K.
__global__ void k_cvtA(const float* __restrict__ ext, int sel0, int str0,
                       int strT, int K, int Kpad) {
    long long idx = (long long)blockIdx.x * blockDim.x + threadIdx.x;
    long long total = (long long)NN * Kpad;
    if (idx >= total) return;
    int kk = (int)(idx % Kpad);
    long long m = idx / Kpad;
    float v = 0.0f;
    if (kk < K) v = (selbuf(sel0, ext))[m * str0 + kk];
    else if (kk < 2 * K) v = g_tx1[m * strT + kk - K];
    else if (kk < 3 * K) v = g_tx2[m * strT + kk - 2 * K];
    __nv_bfloat16 hi = __float2bfloat16(v);
    __nv_bfloat16 lo = __float2bfloat16(v - __bfloat162float(hi));
    g_Ahi[idx] = hi;
    g_Alo[idx] = lo;
}

// W fp32 [3K, N] -> transposed hi/lo [Npad, Kpad], zero-padded.
__global__ void k_cvtW(const float* __restrict__ W, int K, int N, int Npad, int Kpad) {
    long long idx = (long long)blockIdx.x * blockDim.x + threadIdx.x;
    long long total = (long long)Npad * Kpad;
    if (idx >= total) return;
    int kk = (int)(idx % Kpad);
    int n  = (int)(idx / Kpad);
    float v = (n < N && kk < 3 * K) ? W[(size_t)kk * N + n] : 0.0f;
    __nv_bfloat16 hi = __float2bfloat16(v);
    __nv_bfloat16 lo = __float2bfloat16(v - __bfloat162float(hi));
    g_Wthi[idx] = hi;
    g_Wtlo[idx] = lo;
}

// Layer-1 combined weights: rows n in [0,768): b=n>>8, nn=n&255.
// b0: W0-W2, b1: W1, b2: W2  (w layout [3,512,250]); cols k in [0,512).
__global__ void k_cvtW1(const float* __restrict__ w) {
    long long idx = (long long)blockIdx.x * blockDim.x + threadIdx.x;
    if (idx >= 768LL * 512) return;
    int k = (int)(idx & 511);
    int n = (int)(idx >> 9);
    int b = n >> 8, nn = n & 255;
    float v = 0.0f;
    if (nn < 250) {
        if (b == 0)
            v = w[(size_t)k * 250 + nn] - w[2 * 512 * 250 + (size_t)k * 250 + nn];
        else
            v = w[(size_t)b * 512 * 250 + (size_t)k * 250 + nn];
    }
    __nv_bfloat16 hi = __float2bfloat16(v);
    __nv_bfloat16 lo = __float2bfloat16(v - __bfloat162float(hi));
    g_Wthi[idx] = hi;
    g_Wtlo[idx] = lo;
}

// ---------------- mma.sync GEMM, cp.async 3-stage pipeline -------------------
// C[M,N](ldc) = A·Wt^T (+bias,relu if bias). Optional fp16 mirror.
#define TBM 128
#define TBN 128
#define TBK 32
#define SROW 40
#define OFF_AH 0
#define OFF_AL (TBM * SROW * 2)
#define OFF_BH (2 * TBM * SROW * 2)
#define OFF_BL (2 * TBM * SROW * 2 + TBN * SROW * 2)
#define STAGE_BYTES (2 * (TBM + TBN) * SROW * 2)   // 40960
#define NSTAGE 3
#define SMEM_TOTAL (NSTAGE * STAGE_BYTES)          // 122880

__global__ void __launch_bounds__(256) k_mmagemm(
    const float* __restrict__ bias, float* __restrict__ extC, int selC,
    int M, int N, int ldc, int Kpad, int msel, int mstr) {
    extern __shared__ __align__(16) char dynsm[];
    const uint32_t sbase = smem_to_u32(dynsm);

    float* C = selbuf_mut(selC, extC);
    __half* mir = selh(msel);
    const int tid = threadIdx.x;
    const int wid = tid >> 5, lane = tid & 31;
    const int wm = wid >> 1, wn = wid & 1;
    const int blockM = blockIdx.y * TBM;
    const int blockN = blockIdx.x * TBN;

    const int ldrow = tid >> 2;
    const int ldcol = (tid & 3) * 8;
    const int nch = Kpad / TBK;

    auto prefetch = [&](int kc, int st) {
        uint32_t sb = sbase + st * STAGE_BYTES;
#pragma unroll
        for (int p = 0; p < 2; p++) {
            int row = ldrow + p * 64;
            uint32_t dsto = (uint32_t)(row * SROW + ldcol) * 2;
            int gA = blockM + row;
            int okA = (gA < M) ? 16 : 0;
            size_t aoff = (size_t)gA * Kpad + kc * TBK + ldcol;
            cp16(sb + OFF_AH + dsto, g_Ahi + aoff, okA);
            cp16(sb + OFF_AL + dsto, g_Alo + aoff, okA);
            size_t boff = (size_t)(blockN + row) * Kpad + kc * TBK + ldcol;
            cp16(sb + OFF_BH + dsto, g_Wthi + boff, 16);
            cp16(sb + OFF_BL + dsto, g_Wtlo + boff, 16);
        }
    };

    float acc[2][8][4];
#pragma unroll
    for (int i = 0; i < 2; i++)
#pragma unroll
        for (int j = 0; j < 8; j++)
#pragma unroll
            for (int q = 0; q < 4; q++) acc[i][j][q] = 0.0f;

    prefetch(0, 0);
    CP_COMMIT();
    if (nch > 1) { prefetch(1, 1); CP_COMMIT(); }

    int st = 0;
    for (int kc = 0; kc < nch; kc++) {
        if (kc + 2 < nch) {
            int st2 = st + 2; if (st2 >= NSTAGE) st2 -= NSTAGE;
            prefetch(kc + 2, st2);
            CP_COMMIT();
            CP_WAIT2();
        } else if (kc + 1 < nch) {
            CP_WAIT1();
        } else {
            CP_WAIT0();
        }
        __syncthreads();

        uint32_t sb = sbase + st * STAGE_BYTES;
        uint32_t uAh = sb + OFF_AH, uAl = sb + OFF_AL;
        uint32_t uBh = sb + OFF_BH, uBl = sb + OFF_BL;

#pragma unroll
        for (int ks = 0; ks < TBK; ks += 16) {
            uint32_t Ah[2][4], Al[2][4];
            {
                int arow = wm * 32 + (lane & 15);
                int akof = ks + ((lane >> 4) * 8);
#pragma unroll
                for (int mi = 0; mi < 2; mi++) {
                    uint32_t off = (uint32_t)((arow + mi * 16) * SROW + akof) * 2;
                    ldsm4(Ah[mi], uAh + off);
                    ldsm4(Al[mi], uAl + off);
                }
            }
            uint32_t Bh[8][2], Bl[8][2];
            {
                int bn = wn * 64 + ((lane >> 4) * 8) + (lane & 7);
                int bk = ks + (((lane >> 3) & 1) * 8);
#pragma unroll
                for (int np = 0; np < 4; np++) {
                    uint32_t off = (uint32_t)((bn + np * 16) * SROW + bk) * 2;
                    uint32_t rh[4], rl[4];
                    ldsm4(rh, uBh + off);
                    ldsm4(rl, uBl + off);
                    Bh[np * 2][0] = rh[0]; Bh[np * 2][1] = rh[1];
                    Bh[np * 2 + 1][0] = rh[2]; Bh[np * 2 + 1][1] = rh[3];
                    Bl[np * 2][0] = rl[0]; Bl[np * 2][1] = rl[1];
                    Bl[np * 2 + 1][0] = rl[2]; Bl[np * 2 + 1][1] = rl[3];
                }
            }
#pragma unroll
            for (int mi = 0; mi < 2; mi++)
#pragma unroll
                for (int ni = 0; ni < 8; ni++) {
                    mma_bf16(acc[mi][ni], Ah[mi], Bh[ni]);
                    mma_bf16(acc[mi][ni], Ah[mi], Bl[ni]);
                    mma_bf16(acc[mi][ni], Al[mi], Bh[ni]);
                }
        }
        __syncthreads();
        st++; if (st >= NSTAGE) st = 0;
    }

    // ---- epilogue
    const int g = lane >> 2, t = lane & 3;
#pragma unroll
    for (int mi = 0; mi < 2; mi++) {
        int r0 = blockM + wm * 32 + mi * 16 + g;
#pragma unroll
        for (int ni = 0; ni < 8; ni++) {
            int c0 = blockN + wn * 64 + ni * 8 + 2 * t;
            if (c0 >= N) continue;
            bool c1ok = (c0 + 1) < N;
            float bv0 = bias ? bias[c0] : 0.0f;
            float bv1 = (bias && c1ok) ? bias[c0 + 1] : 0.0f;
#pragma unroll
            for (int h = 0; h < 2; h++) {
                int r = r0 + h * 8;
                if (r >= M) continue;
                float v0 = acc[mi][ni][2 * h] + bv0;
                if (bias) v0 = v0 > 0.f ? v0 : 0.f;
                C[(size_t)r * ldc + c0] = v0;
                if (mir) mir[(size_t)r * mstr + c0] = __float2half_rn(v0);
                if (c1ok) {
                    float v1 = acc[mi][ni][2 * h + 1] + bv1;
                    if (bias) v1 = v1 > 0.f ? v1 : 0.f;
                    C[(size_t)r * ldc + c0 + 1] = v1;
                    if (mir) mir[(size_t)r * mstr + c0 + 1] = __float2half_rn(v1);
                }
            }
        }
    }
}

// ---------------- orchestration ---------------------------------------------
extern "C" void kernel_launch(void* const* d_in, const int* in_sizes, int n_in,
                              void* d_out, int out_size) {
    const float* x  = (const float*)d_in[0];
    const void*  ei = d_in[1];
    const float* w1 = (const float*)d_in[2];
    const float* b1 = (const float*)d_in[3];
    const float* w2 = (const float*)d_in[4];
    const float* b2 = (const float*)d_in[5];
    const float* w3 = (const float*)d_in[6];
    const float* b3 = (const float*)d_in[7];
    float* out = (float*)d_out;
    int E = in_sizes[1] / 2;

    cudaFuncSetAttribute(k_mmagemm, cudaFuncAttributeMaxDynamicSharedMemorySize,
                         SMEM_TOTAL);

    int nb = (NN + 255) / 256;
    int eb = (E + 255) / 256;
    k_detect<<<1, 32>>>((const int*)ei);
    k_zero_deg<<<nb, 256>>>();
    k_count<<<eb, 256>>>(ei, E);
    k_dis<<<nb, 256>>>();
    k_scan<<<1, 1024>>>();
    k_cursor<<<nb, 256>>>();
    k_fill<<<eb, 256>>>(ei, E);

    int spb = (NN * 32 + 255) / 256;
    int mt = (NN + TBM - 1) / TBM;   // 391

    // ==== layer 1 (GEMM first, SpMMs at width 250) ====
    // U = x @ [W0-W2 | W1 | W2]^T -> g_u fp32 (str 768) + mirror g_f16a (768)
    {
        long long tA = (long long)NN * 512;
        k_cvtA<<<(unsigned)((tA + 255) / 256), 256>>>(x, 0, 512, 512, 512, 512);
        k_cvtW1<<<(unsigned)((768LL * 512 + 255) / 256), 256>>>(w1);
        dim3 g(768 / TBN, mt);
        k_mmagemm<<<g, 256, SMEM_TOTAL>>>(nullptr, nullptr, 5, NN, 768, 768, 512,
                                          6, 768);
    }
    // v = u1 + 2*Lhat(u2) -> tx1 (str 256) + mirror g_f16b (256)
    k_spmmh<250><<<spb, 256>>>(6, 512, 768, nullptr, 5, 512, 768, 5, 256, 768,
                               1, 256, 2.0f, 1.0f, nullptr, 0, 7, 256);
    // h1 = relu(u0 + Lhat(v) + b1) -> h1 (str 256) + mirror g_f16a (256)
    k_spmmh<250><<<spb, 256>>>(7, 0, 256, nullptr, 1, 0, 256, 5, 0, 768,
                               3, 256, 1.0f, 1.0f, b1, 1, 6, 256);

    // ==== layer 2: SpMM width 250, GEMM K=250 (Kpad 768), N=500 ====
    // tx1 = Lhat(h1) + mirror g_f16b
    k_spmmh<250><<<spb, 256>>>(6, 0, 256, nullptr, 3, 0, 256, 3, 0, 256,
                               1, 256, 1.0f, 0.0f, nullptr, 0, 7, 256);
    // tx2 = 2*Lhat(tx1) - h1
    k_spmmh<250><<<spb, 256>>>(7, 0, 256, nullptr, 1, 0, 256, 3, 0, 256,
                               2, 256, 2.0f, -1.0f, nullptr, 0, 0, 0);
    {
        long long tA = (long long)NN * 768;
        k_cvtA<<<(unsigned)((tA + 255) / 256), 256>>>(nullptr, 3, 256, 256, 250, 768);
        long long tW = 512LL * 768;
        k_cvtW<<<(unsigned)((tW + 255) / 256), 256>>>(w2, 250, 500, 512, 768);
        dim3 g(512 / TBN, mt);
        // h2 fp32 (ldc 500) + mirror g_f16a (512)
        k_mmagemm<<<g, 256, SMEM_TOTAL>>>(b2, nullptr, 4, NN, 500, 500, 768,
                                          6, 512);
    }

    // ==== layer 3: SpMM width 500, GEMM K=500 (Kpad 1536), N=1000 ====
    // tx1 = Lhat(h2) (str 512) + mirror g_f16b (512)
    k_spmmh<500><<<spb, 256>>>(6, 0, 512, nullptr, 4, 0, 500, 4, 0, 500,
                               1, 512, 1.0f, 0.0f, nullptr, 0, 7, 512);
    // tx2 = 2*Lhat(tx1) - h2 (str 512)
    k_spmmh<500><<<spb, 256>>>(7, 0, 512, nullptr, 1, 0, 512, 4, 0, 500,
                               2, 512, 2.0f, -1.0f, nullptr, 0, 0, 0);
    {
        long long tA = (long long)NN * 1536;
        k_cvtA<<<(unsigned)((tA + 255) / 256), 256>>>(nullptr, 4, 500, 512, 500, 1536);
        long long tW = 1024LL * 1536;
        k_cvtW<<<(unsigned)((tW + 255) / 256), 256>>>(w3, 500, 1000, 1024, 1536);
        dim3 g(1024 / TBN, mt);
        k_mmagemm<<<g, 256, SMEM_TOTAL>>>(b3, out, 0, NN, 1000, 1000, 1536, 0, 0);
    }
}

// round 14
// speedup vs baseline: 1.7692x; 1.7692x over previous
#include <cuda_runtime.h>
#include <cuda_bf16.h>
#include <cstdint>

#define NN 50000
#define MAXE 1600000
#define KPADMAX 1536

// ---------------- scratch (static device globals) ---------------------------
__device__ __align__(16) float g_tx1[NN * 512];
__device__ __align__(16) float g_tx2[NN * 512];
__device__ __align__(16) float g_h1 [NN * 252];   // stride 250 used
__device__ __align__(16) float g_h2 [NN * 500];
__device__ __align__(16) float g_u  [NN * 768];   // layer-1 GEMM out [u0|u1|u2]
__device__ __align__(16) __nv_bfloat16 g_Ahi[(size_t)NN * KPADMAX];
__device__ __align__(16) __nv_bfloat16 g_Alo[(size_t)NN * KPADMAX];
__device__ __align__(16) __nv_bfloat16 g_Wthi[1024 * KPADMAX];
__device__ __align__(16) __nv_bfloat16 g_Wtlo[1024 * KPADMAX];
__device__ int   g_deg[NN];
__device__ int   g_rowptr[NN + 1];
__device__ int   g_cursor[NN];
__device__ int   g_colidx[MAXE];
__device__ float g_dis[NN];
__device__ float g_diag[NN];
__device__ int   g_is64;

__device__ __forceinline__ const float* selbuf(int sel, const float* ext) {
    switch (sel) {
        case 1: return g_tx1;
        case 2: return g_tx2;
        case 3: return g_h1;
        case 4: return g_h2;
        case 5: return g_u;
        default: return ext;
    }
}
__device__ __forceinline__ float* selbuf_mut(int sel, float* ext) {
    switch (sel) {
        case 1: return g_tx1;
        case 2: return g_tx2;
        case 3: return g_h1;
        case 4: return g_h2;
        case 5: return g_u;
        default: return ext;
    }
}

__device__ __forceinline__ int edge_at(const void* ei, int E, long long idx) {
    if (g_is64) return (int)((const long long*)ei)[idx];
    return ((const int*)ei)[idx];
}

__device__ __forceinline__ uint32_t smem_to_u32(const void* p) {
    uint32_t a;
    asm("{ .reg .u64 t; cvta.to.shared.u64 t, %1; cvt.u32.u64 %0, t; }"
        : "=r"(a) : "l"(p));
    return a;
}

// mma.sync bf16 (sm_80 path; legal on plain sm_103 target)
__device__ __forceinline__ void mma_bf16(float* c, const uint32_t* a, const uint32_t* b) {
    asm volatile("mma.sync.aligned.m16n8k16.row.col.f32.bf16.bf16.f32 "
        "{%0,%1,%2,%3}, {%4,%5,%6,%7}, {%8,%9}, {%0,%1,%2,%3};"
        : "+f"(c[0]), "+f"(c[1]), "+f"(c[2]), "+f"(c[3])
        : "r"(a[0]), "r"(a[1]), "r"(a[2]), "r"(a[3]), "r"(b[0]), "r"(b[1]));
}
__device__ __forceinline__ void ldsm4(uint32_t* r, uint32_t addr) {
    asm volatile("ldmatrix.sync.aligned.m8n8.x4.shared.b16 {%0,%1,%2,%3}, [%4];"
        : "=r"(r[0]), "=r"(r[1]), "=r"(r[2]), "=r"(r[3]) : "r"(addr));
}
__device__ __forceinline__ void cp16(uint32_t dst, const void* src, int src_bytes) {
    asm volatile("cp.async.cg.shared.global [%0], [%1], 16, %2;"
                 :: "r"(dst), "l"(src), "r"(src_bytes));
}
#define CP_COMMIT() asm volatile("cp.async.commit_group;" ::: "memory")
#define CP_WAIT1()  asm volatile("cp.async.wait_group 1;" ::: "memory")
#define CP_WAIT0()  asm volatile("cp.async.wait_group 0;" ::: "memory")

// pack two floats' bf16-hi parts / lo parts into one u32
__device__ __forceinline__ uint32_t pack_hi2(float x, float y) {
    __nv_bfloat162 h;
    h.x = __float2bfloat16(x);
    h.y = __float2bfloat16(y);
    return *(const uint32_t*)&h;
}
__device__ __forceinline__ uint32_t pack_lo2(float x, float y, uint32_t hi) {
    const __nv_bfloat162* hp = (const __nv_bfloat162*)&hi;
    __nv_bfloat162 l;
    l.x = __float2bfloat16(x - __bfloat162float(hp->x));
    l.y = __float2bfloat16(y - __bfloat162float(hp->y));
    return *(const uint32_t*)&l;
}

// ---------------- prep kernels ----------------------------------------------
// detect int64-vs-int32 edge buffer + zero degree array (fused)
__global__ void k_dzero(const int* __restrict__ ei32) {
    int i = blockIdx.x * blockDim.x + threadIdx.x;
    if (i < NN) g_deg[i] = 0;
    if (blockIdx.x == 0 && threadIdx.x == 0) {
        int all0 = 1;
        for (int q = 0; q < 64; q++)
            if (ei32[2 * q + 1] != 0) { all0 = 0; break; }
        g_is64 = all0;
    }
}

__global__ void k_count(const void* __restrict__ ei, int E) {
    int e = blockIdx.x * blockDim.x + threadIdx.x;
    if (e < E) {
        int dst = edge_at(ei, E, (long long)E + e);
        if ((unsigned)dst < NN) atomicAdd(&g_deg[dst], 1);
    }
}

// dis + single-block scan + cursor (fused, 1 block x 1024)
__global__ void k_dsc() {
    for (int i = threadIdx.x; i < NN; i += 1024) {
        int d = g_deg[i];
        g_dis[i]  = d > 0 ? rsqrtf((float)d) : 0.0f;
        g_diag[i] = d > 0 ? 0.0f : -1.0f;
    }
    __shared__ int sm[1024];
    __shared__ int carry;
    if (threadIdx.x == 0) { carry = 0; g_rowptr[0] = 0; }
    __syncthreads();
    for (int base = 0; base < NN; base += 1024) {
        int i = base + threadIdx.x;
        int v = (i < NN) ? g_deg[i] : 0;
        sm[threadIdx.x] = v;
        __syncthreads();
        for (int off = 1; off < 1024; off <<= 1) {
            int t = (threadIdx.x >= off) ? sm[threadIdx.x - off] : 0;
            __syncthreads();
            sm[threadIdx.x] += t;
            __syncthreads();
        }
        if (i < NN) g_rowptr[i + 1] = carry + sm[threadIdx.x];
        __syncthreads();
        if (threadIdx.x == 0) carry += sm[1023];
        __syncthreads();
    }
    for (int i = threadIdx.x; i < NN; i += 1024) g_cursor[i] = g_rowptr[i];
}

__global__ void k_fill(const void* __restrict__ ei, int E) {
    int e = blockIdx.x * blockDim.x + threadIdx.x;
    if (e < E) {
        int dst = edge_at(ei, E, (long long)E + e);
        int src = edge_at(ei, E, e);
        if ((unsigned)dst < NN && (unsigned)src < NN) {
            int pos = atomicAdd(&g_cursor[dst], 1);
            if ((unsigned)pos < MAXE) g_colidx[pos] = src;
        }
    }
}

// zero gap/pad strips of layer-2 A layout (cols 250,251,502,503,754..767)
__global__ void k_zp2() {
    long long idx = (long long)blockIdx.x * blockDim.x + threadIdx.x;
    if (idx >= (long long)NN * 18) return;
    int row = (int)(idx / 18);
    int j = (int)(idx % 18);
    int col = (j < 2) ? 250 + j : (j < 4 ? 500 + j : 750 + j);
    size_t o = (size_t)row * 768 + col;
    g_Ahi[o] = __float2bfloat16(0.0f);
    g_Alo[o] = __float2bfloat16(0.0f);
}
// zero pad of layer-3 A layout (cols 1500..1535)
__global__ void k_zp3() {
    long long idx = (long long)blockIdx.x * blockDim.x + threadIdx.x;
    if (idx >= (long long)NN * 36) return;
    int row = (int)(idx / 36);
    int col = 1500 + (int)(idx % 36);
    size_t o = (size_t)row * 1536 + col;
    g_Ahi[o] = __float2bfloat16(0.0f);
    g_Alo[o] = __float2bfloat16(0.0f);
}

// ---------------- SpMM (warp per dst row, CSR; float2 lanes) ----------------
// out = mul*(diag[row]*in[row] - dis[row]*sum(dis[s]*in[s])) + subcoef*sub[row]
// (+bias, relu).  If astr != 0: also write bf16 hi/lo of result into
// g_Ahi/g_Alo at [row*astr + aoff + f].
template <int F>
__global__ void k_spmm2(const float* __restrict__ ext,
                        int sel_in, int off_in, int str_in,
                        int sel_sub, int off_sub, int str_sub,
                        int sel_out, int str_out,
                        float mul, float subcoef,
                        const float* __restrict__ bias, int do_relu,
                        int aoff, int astr) {
    constexpr int NH = F / 2;
    constexpr int NR = (NH + 31) / 32;
    const float* hin  = selbuf(sel_in, ext) + off_in;
    const float* hsub = selbuf(sel_sub, ext) + off_sub;
    float* out = selbuf_mut(sel_out, nullptr);

    int warp = (blockIdx.x * blockDim.x + threadIdx.x) >> 5;
    int lane = threadIdx.x & 31;
    if (warp >= NN) return;
    int row = warp;
    int s = g_rowptr[row], e = g_rowptr[row + 1];

    float2 acc[NR];
#pragma unroll
    for (int r = 0; r < NR; r++) acc[r] = make_float2(0.f, 0.f);

    for (int j = s; j < e; j++) {
        int src = g_colidx[j];
        float ws = g_dis[src];
        const float2* hp = (const float2*)(hin + (size_t)src * str_in);
#pragma unroll
        for (int r = 0; r < NR; r++) {
            int f2 = lane + r * 32;
            if ((NH & 31) == 0 || f2 < NH) {
                float2 v = hp[f2];
                acc[r].x += ws * v.x;
                acc[r].y += ws * v.y;
            }
        }
    }

    float di = g_dis[row], dg = g_diag[row];
    const float2* hr = (const float2*)(hin + (size_t)row * str_in);
    const float2* sr = (const float2*)(hsub + (size_t)row * str_sub);
    float2* orow = (float2*)(out + (size_t)row * str_out);
    uint32_t* ahr = astr ? (uint32_t*)(g_Ahi + (size_t)row * astr + aoff) : nullptr;
    uint32_t* alr = astr ? (uint32_t*)(g_Alo + (size_t)row * astr + aoff) : nullptr;
#pragma unroll
    for (int r = 0; r < NR; r++) {
        int f2 = lane + r * 32;
        if ((NH & 31) == 0 || f2 < NH) {
            float2 h = hr[f2];
            float vx = mul * (dg * h.x - di * acc[r].x);
            float vy = mul * (dg * h.y - di * acc[r].y);
            if (subcoef != 0.0f) {
                float2 sv = sr[f2];
                vx += subcoef * sv.x;
                vy += subcoef * sv.y;
            }
            if (bias) {
                vx += bias[2 * f2];
                vy += bias[2 * f2 + 1];
            }
            if (do_relu) {
                vx = vx > 0.f ? vx : 0.f;
                vy = vy > 0.f ? vy : 0.f;
            }
            orow[f2] = make_float2(vx, vy);
            if (astr) {
                uint32_t hp2 = pack_hi2(vx, vy);
                ahr[f2] = hp2;
                alr[f2] = pack_lo2(vx, vy, hp2);
            }
        }
    }
}

// ---------------- bf16 conversion kernels ------------------------------------
// layer-1 A: x fp32 [NN,512] -> hi/lo [NN,512]
__global__ void k_cvtA1(const float* __restrict__ x) {
    long long idx = (long long)blockIdx.x * blockDim.x + threadIdx.x;
    if (idx >= (long long)NN * 512) return;
    float v = x[idx];
    __nv_bfloat16 hi = __float2bfloat16(v);
    g_Ahi[idx] = hi;
    g_Alo[idx] = __float2bfloat16(v - __bfloat162float(hi));
}

// layer-3 A block 0: h2 [NN,500] -> hi/lo at [m*1536 + k], k<500
__global__ void k_cvtA3(void) {
    long long idx = (long long)blockIdx.x * blockDim.x + threadIdx.x;
    if (idx >= (long long)NN * 500) return;
    int m = (int)(idx / 500);
    int k = (int)(idx % 500);
    float v = g_h2[(size_t)m * 500 + k];
    __nv_bfloat16 hi = __float2bfloat16(v);
    size_t o = (size_t)m * 1536 + k;
    g_Ahi[o] = hi;
    g_Alo[o] = __float2bfloat16(v - __bfloat162float(hi));
}

// generic W: fp32 [3K,N] -> transposed hi/lo [Npad,Kpad] (layer 3)
__global__ void k_cvtW(const float* __restrict__ W, int K, int N, int Npad, int Kpad) {
    long long idx = (long long)blockIdx.x * blockDim.x + threadIdx.x;
    long long total = (long long)Npad * Kpad;
    if (idx >= total) return;
    int kk = (int)(idx % Kpad);
    int n  = (int)(idx / Kpad);
    float v = (n < N && kk < 3 * K) ? W[(size_t)kk * N + n] : 0.0f;
    __nv_bfloat16 hi = __float2bfloat16(v);
    g_Wthi[idx] = hi;
    g_Wtlo[idx] = __float2bfloat16(v - __bfloat162float(hi));
}

// layer-1 combined weights: rows n in [0,768): b=n>>8, nn=n&255.
// b0: W0-W2, b1: W1, b2: W2 (w layout [3,512,250]); cols k in [0,512).
__global__ void k_cvtW1(const float* __restrict__ w) {
    long long idx = (long long)blockIdx.x * blockDim.x + threadIdx.x;
    if (idx >= 768LL * 512) return;
    int k = (int)(idx & 511);
    int n = (int)(idx >> 9);
    int b = n >> 8, nn = n & 255;
    float v = 0.0f;
    if (nn < 250) {
        if (b == 0)
            v = w[(size_t)k * 250 + nn] - w[2 * 512 * 250 + (size_t)k * 250 + nn];
        else
            v = w[(size_t)b * 512 * 250 + (size_t)k * 250 + nn];
    }
    __nv_bfloat16 hi = __float2bfloat16(v);
    g_Wthi[idx] = hi;
    g_Wtlo[idx] = __float2bfloat16(v - __bfloat162float(hi));
}

// layer-2 W with gap-aligned k mapping: kk in [0,250)->k3=kk;
// [252,502)->k3=kk-2; [504,754)->k3=kk-4; else 0. (w2 = [750,500] row-major)
__global__ void k_cvtW2(const float* __restrict__ w) {
    long long idx = (long long)blockIdx.x * blockDim.x + threadIdx.x;
    if (idx >= 512LL * 768) return;
    int kk = (int)(idx % 768);
    int n  = (int)(idx / 768);
    float v = 0.0f;
    if (n < 500) {
        int k3 = -1;
        if (kk < 250) k3 = kk;
        else if (kk >= 252 && kk < 502) k3 = kk - 2;
        else if (kk >= 504 && kk < 754) k3 = kk - 4;
        if (k3 >= 0) v = w[(size_t)k3 * 500 + n];
    }
    __nv_bfloat16 hi = __float2bfloat16(v);
    g_Wthi[idx] = hi;
    g_Wtlo[idx] = __float2bfloat16(v - __bfloat162float(hi));
}

// ---------------- mma.sync GEMM, cp.async double-buffered (R9 version) ------
#define TBM 128
#define TBN 128
#define TBK 32
#define SROW 40
#define OFF_AH 0
#define OFF_AL (TBM * SROW * 2)
#define OFF_BH (2 * TBM * SROW * 2)
#define OFF_BL (2 * TBM * SROW * 2 + TBN * SROW * 2)
#define STAGE_BYTES (2 * (TBM + TBN) * SROW * 2)   // 40960
#define SMEM_TOTAL (2 * STAGE_BYTES)               // 81920

__global__ void __launch_bounds__(256) k_mmagemm(
    const float* __restrict__ bias, float* __restrict__ extC, int selC,
    int M, int N, int Kpad) {
    extern __shared__ __align__(16) char dynsm[];
    const uint32_t sbase = smem_to_u32(dynsm);

    float* C = selbuf_mut(selC, extC);
    const int tid = threadIdx.x;
    const int wid = tid >> 5, lane = tid & 31;
    const int wm = wid >> 1, wn = wid & 1;
    const int blockM = blockIdx.y * TBM;
    const int blockN = blockIdx.x * TBN;

    const int ldrow = tid >> 2;
    const int ldcol = (tid & 3) * 8;
    const int nch = Kpad / TBK;

    auto prefetch = [&](int kc, int st) {
        uint32_t sb = sbase + st * STAGE_BYTES;
#pragma unroll
        for (int p = 0; p < 2; p++) {
            int row = ldrow + p * 64;
            uint32_t dsto = (uint32_t)(row * SROW + ldcol) * 2;
            int gA = blockM + row;
            int okA = (gA < M) ? 16 : 0;
            size_t aoff = (size_t)gA * Kpad + kc * TBK + ldcol;
            cp16(sb + OFF_AH + dsto, g_Ahi + aoff, okA);
            cp16(sb + OFF_AL + dsto, g_Alo + aoff, okA);
            size_t boff = (size_t)(blockN + row) * Kpad + kc * TBK + ldcol;
            cp16(sb + OFF_BH + dsto, g_Wthi + boff, 16);
            cp16(sb + OFF_BL + dsto, g_Wtlo + boff, 16);
        }
    };

    float acc[2][8][4];
#pragma unroll
    for (int i = 0; i < 2; i++)
#pragma unroll
        for (int j = 0; j < 8; j++)
#pragma unroll
            for (int q = 0; q < 4; q++) acc[i][j][q] = 0.0f;

    prefetch(0, 0);
    CP_COMMIT();

    for (int kc = 0; kc < nch; kc++) {
        int st = kc & 1;
        if (kc + 1 < nch) {
            prefetch(kc + 1, st ^ 1);
            CP_COMMIT();
            CP_WAIT1();
        } else {
            CP_WAIT0();
        }
        __syncthreads();

        uint32_t sb = sbase + st * STAGE_BYTES;
        uint32_t uAh = sb + OFF_AH, uAl = sb + OFF_AL;
        uint32_t uBh = sb + OFF_BH, uBl = sb + OFF_BL;

#pragma unroll
        for (int ks = 0; ks < TBK; ks += 16) {
            uint32_t Ah[2][4], Al[2][4];
            {
                int arow = wm * 32 + (lane & 15);
                int akof = ks + ((lane >> 4) * 8);
#pragma unroll
                for (int mi = 0; mi < 2; mi++) {
                    uint32_t off = (uint32_t)((arow + mi * 16) * SROW + akof) * 2;
                    ldsm4(Ah[mi], uAh + off);
                    ldsm4(Al[mi], uAl + off);
                }
            }
            uint32_t Bh[8][2], Bl[8][2];
            {
                int bn = wn * 64 + ((lane >> 4) * 8) + (lane & 7);
                int bk = ks + (((lane >> 3) & 1) * 8);
#pragma unroll
                for (int np = 0; np < 4; np++) {
                    uint32_t off = (uint32_t)((bn + np * 16) * SROW + bk) * 2;
                    uint32_t rh[4], rl[4];
                    ldsm4(rh, uBh + off);
                    ldsm4(rl, uBl + off);
                    Bh[np * 2][0] = rh[0]; Bh[np * 2][1] = rh[1];
                    Bh[np * 2 + 1][0] = rh[2]; Bh[np * 2 + 1][1] = rh[3];
                    Bl[np * 2][0] = rl[0]; Bl[np * 2][1] = rl[1];
                    Bl[np * 2 + 1][0] = rl[2]; Bl[np * 2 + 1][1] = rl[3];
                }
            }
#pragma unroll
            for (int mi = 0; mi < 2; mi++)
#pragma unroll
                for (int ni = 0; ni < 8; ni++) {
                    mma_bf16(acc[mi][ni], Ah[mi], Bh[ni]);
                    mma_bf16(acc[mi][ni], Ah[mi], Bl[ni]);
                    mma_bf16(acc[mi][ni], Al[mi], Bh[ni]);
                }
        }
        __syncthreads();
    }

    // ---- epilogue
    const int g = lane >> 2, t = lane & 3;
#pragma unroll
    for (int mi = 0; mi < 2; mi++) {
        int r0 = blockM + wm * 32 + mi * 16 + g;
#pragma unroll
        for (int ni = 0; ni < 8; ni++) {
            int c0 = blockN + wn * 64 + ni * 8 + 2 * t;
            if (c0 >= N) continue;
            bool c1ok = (c0 + 1) < N;
            float bv0 = bias ? bias[c0] : 0.0f;
            float bv1 = (bias && c1ok) ? bias[c0 + 1] : 0.0f;
            if (r0 < M) {
                float v0 = acc[mi][ni][0] + bv0;
                if (bias) v0 = v0 > 0.f ? v0 : 0.f;
                C[(size_t)r0 * N + c0] = v0;
                if (c1ok) {
                    float v1 = acc[mi][ni][1] + bv1;
                    if (bias) v1 = v1 > 0.f ? v1 : 0.f;
                    C[(size_t)r0 * N + c0 + 1] = v1;
                }
            }
            if (r0 + 8 < M) {
                float v2 = acc[mi][ni][2] + bv0;
                if (bias) v2 = v2 > 0.f ? v2 : 0.f;
                C[(size_t)(r0 + 8) * N + c0] = v2;
                if (c1ok) {
                    float v3 = acc[mi][ni][3] + bv1;
                    if (bias) v3 = v3 > 0.f ? v3 : 0.f;
                    C[(size_t)(r0 + 8) * N + c0 + 1] = v3;
                }
            }
        }
    }
}

// ---------------- orchestration ---------------------------------------------
extern "C" void kernel_launch(void* const* d_in, const int* in_sizes, int n_in,
                              void* d_out, int out_size) {
    const float* x  = (const float*)d_in[0];
    const void*  ei = d_in[1];
    const float* w1 = (const float*)d_in[2];
    const float* b1 = (const float*)d_in[3];
    const float* w2 = (const float*)d_in[4];
    const float* b2 = (const float*)d_in[5];
    const float* w3 = (const float*)d_in[6];
    const float* b3 = (const float*)d_in[7];
    float* out = (float*)d_out;
    int E = in_sizes[1] / 2;

    cudaFuncSetAttribute(k_mmagemm, cudaFuncAttributeMaxDynamicSharedMemorySize,
                         SMEM_TOTAL);

    int nb = (NN + 255) / 256;
    int eb = (E + 255) / 256;
    int spb = (NN * 32 + 255) / 256;
    int mt = (NN + TBM - 1) / TBM;   // 391

    // (1) layer-1 A convert    (2) layer-1 W convert
    k_cvtA1<<<(unsigned)(((long long)NN * 512 + 255) / 256), 256>>>(x);
    k_cvtW1<<<(unsigned)((768LL * 512 + 255) / 256), 256>>>(w1);
    // (3) detect + zero degree
    k_dzero<<<nb, 256>>>((const int*)ei);
    // (4) layer-1 GEMM: U = x @ [W0-W2 | W1 | W2]^T  -> g_u [NN,768]
    {
        dim3 g(768 / TBN, mt);
        k_mmagemm<<<g, 256, SMEM_TOTAL>>>(nullptr, nullptr, 5, NN, 768, 512);
    }
    // (5..8) graph prep + layer-2 A gap zeroing
    k_count<<<eb, 256>>>(ei, E);
    k_dsc<<<1, 1024>>>();
    k_fill<<<eb, 256>>>(ei, E);
    k_zp2<<<(unsigned)(((long long)NN * 18 + 255) / 256), 256>>>();

    // (9) v = u1 + 2*Lhat(u2)  -> tx1 (str 250)
    k_spmm2<250><<<spb, 256>>>(nullptr, 5, 512, 768, 5, 256, 768, 1, 250,
                               2.0f, 1.0f, nullptr, 0, 0, 0);
    // (10) h1 = relu(u0 + Lhat(v) + b1) -> h1 + A2-block0
    k_spmm2<250><<<spb, 256>>>(nullptr, 1, 0, 250, 5, 0, 768, 3, 250,
                               1.0f, 1.0f, b1, 1, 0, 768);
    // (11) tx1 = Lhat(h1) + A2-block1 @252
    k_spmm2<250><<<spb, 256>>>(nullptr, 3, 0, 250, 3, 0, 250, 1, 250,
                               1.0f, 0.0f, nullptr, 0, 252, 768);
    // (12) tx2 = 2*Lhat(tx1) - h1 + A2-block2 @504
    k_spmm2<250><<<spb, 256>>>(nullptr, 1, 0, 250, 3, 0, 250, 2, 250,
                               2.0f, -1.0f, nullptr, 0, 504, 768);
    // (13) layer-2 W convert, (14) layer-2 GEMM -> h2 [NN,500]
    k_cvtW2<<<(unsigned)((512LL * 768 + 255) / 256), 256>>>(w2);
    {
        dim3 g(512 / TBN, mt);
        k_mmagemm<<<g, 256, SMEM_TOTAL>>>(b2, nullptr, 4, NN, 500, 768);
    }
    // (15) layer-3 pad zeroing, (16) h2 -> A3-block0
    k_zp3<<<(unsigned)(((long long)NN * 36 + 255) / 256), 256>>>();
    k_cvtA3<<<(unsigned)(((long long)NN * 500 + 255) / 256), 256>>>();
    // (17) tx1 = Lhat(h2) + A3-block1 @500
    k_spmm2<500><<<spb, 256>>>(nullptr, 4, 0, 500, 4, 0, 500, 1, 500,
                               1.0f, 0.0f, nullptr, 0, 500, 1536);
    // (18) tx2 = 2*Lhat(tx1) - h2 + A3-block2 @1000
    k_spmm2<500><<<spb, 256>>>(nullptr, 1, 0, 500, 4, 0, 500, 2, 500,
                               2.0f, -1.0f, nullptr, 0, 1000, 1536);
    // (19) layer-3 W convert, (20) layer-3 GEMM -> out
    {
        long long tW = 1024LL * 1536;
        k_cvtW<<<(unsigned)((tW + 255) / 256), 256>>>(w3, 500, 1000, 1024, 1536);
        dim3 g(1024 / TBN, mt);
        k_mmagemm<<<g, 256, SMEM_TOTAL>>>(b3, out, 0, NN, 1000, 1536);
    }
}

// round 15
// speedup vs baseline: 2.1843x; 1.2347x over previous
#include <cuda_runtime.h>
#include <cuda_fp16.h>
#include <cstdint>

#define NN 50000
#define MAXE 1600000
#define KPADMAX 1536

// ---------------- scratch (static device globals) ---------------------------
__device__ __align__(16) float g_tx1[NN * 512];
__device__ __align__(16) float g_tx2[NN * 512];
__device__ __align__(16) float g_h1 [NN * 252];   // stride 250 used
__device__ __align__(16) float g_h2 [NN * 500];
__device__ __align__(16) float g_u  [NN * 768];   // layer-1 GEMM out [u0|u1|u2]
__device__ __align__(16) __half g_Ahi[(size_t)NN * KPADMAX];
__device__ __align__(16) __half g_Alo[(size_t)NN * KPADMAX];
__device__ __align__(16) __half g_Wt [1024 * KPADMAX];
__device__ int   g_deg[NN];
__device__ int   g_rowptr[NN + 1];
__device__ int   g_cursor[NN];
__device__ int   g_colidx[MAXE];
__device__ float g_dis[NN];
__device__ float g_diag[NN];
__device__ int   g_is64;

__device__ __forceinline__ const float* selbuf(int sel, const float* ext) {
    switch (sel) {
        case 1: return g_tx1;
        case 2: return g_tx2;
        case 3: return g_h1;
        case 4: return g_h2;
        case 5: return g_u;
        default: return ext;
    }
}
__device__ __forceinline__ float* selbuf_mut(int sel, float* ext) {
    switch (sel) {
        case 1: return g_tx1;
        case 2: return g_tx2;
        case 3: return g_h1;
        case 4: return g_h2;
        case 5: return g_u;
        default: return ext;
    }
}

__device__ __forceinline__ int edge_at(const void* ei, int E, long long idx) {
    if (g_is64) return (int)((const long long*)ei)[idx];
    return ((const int*)ei)[idx];
}

__device__ __forceinline__ uint32_t smem_to_u32(const void* p) {
    uint32_t a;
    asm("{ .reg .u64 t; cvta.to.shared.u64 t, %1; cvt.u32.u64 %0, t; }"
        : "=r"(a) : "l"(p));
    return a;
}

// mma.sync fp16 (sm_80 path; legal on plain sm_103 target)
__device__ __forceinline__ void mma_f16(float* c, const uint32_t* a, const uint32_t* b) {
    asm volatile("mma.sync.aligned.m16n8k16.row.col.f32.f16.f16.f32 "
        "{%0,%1,%2,%3}, {%4,%5,%6,%7}, {%8,%9}, {%0,%1,%2,%3};"
        : "+f"(c[0]), "+f"(c[1]), "+f"(c[2]), "+f"(c[3])
        : "r"(a[0]), "r"(a[1]), "r"(a[2]), "r"(a[3]), "r"(b[0]), "r"(b[1]));
}
__device__ __forceinline__ void ldsm4(uint32_t* r, uint32_t addr) {
    asm volatile("ldmatrix.sync.aligned.m8n8.x4.shared.b16 {%0,%1,%2,%3}, [%4];"
        : "=r"(r[0]), "=r"(r[1]), "=r"(r[2]), "=r"(r[3]) : "r"(addr));
}
__device__ __forceinline__ void cp16(uint32_t dst, const void* src, int src_bytes) {
    asm volatile("cp.async.cg.shared.global [%0], [%1], 16, %2;"
                 :: "r"(dst), "l"(src), "r"(src_bytes));
}
#define CP_COMMIT() asm volatile("cp.async.commit_group;" ::: "memory")
#define CP_WAIT1()  asm volatile("cp.async.wait_group 1;" ::: "memory")
#define CP_WAIT0()  asm volatile("cp.async.wait_group 0;" ::: "memory")

// pack two floats' fp16-hi parts / lo residuals into one u32
__device__ __forceinline__ uint32_t pack_hi2(float x, float y) {
    __half2 h;
    h.x = __float2half(x);
    h.y = __float2half(y);
    return *(const uint32_t*)&h;
}
__device__ __forceinline__ uint32_t pack_lo2(float x, float y, uint32_t hi) {
    const __half2* hp = (const __half2*)&hi;
    __half2 l;
    l.x = __float2half(x - __half2float(hp->x));
    l.y = __float2half(y - __half2float(hp->y));
    return *(const uint32_t*)&l;
}

// ---------------- prep kernels ----------------------------------------------
__global__ void k_dzero(const int* __restrict__ ei32) {
    int i = blockIdx.x * blockDim.x + threadIdx.x;
    if (i < NN) g_deg[i] = 0;
    if (blockIdx.x == 0 && threadIdx.x == 0) {
        int all0 = 1;
        for (int q = 0; q < 64; q++)
            if (ei32[2 * q + 1] != 0) { all0 = 0; break; }
        g_is64 = all0;
    }
}

__global__ void k_count(const void* __restrict__ ei, int E) {
    int e = blockIdx.x * blockDim.x + threadIdx.x;
    if (e < E) {
        int dst = edge_at(ei, E, (long long)E + e);
        if ((unsigned)dst < NN) atomicAdd(&g_deg[dst], 1);
    }
}

// dis + single-block scan + cursor (fused, 1 block x 1024)
__global__ void k_dsc() {
    for (int i = threadIdx.x; i < NN; i += 1024) {
        int d = g_deg[i];
        g_dis[i]  = d > 0 ? rsqrtf((float)d) : 0.0f;
        g_diag[i] = d > 0 ? 0.0f : -1.0f;
    }
    __shared__ int sm[1024];
    __shared__ int carry;
    if (threadIdx.x == 0) { carry = 0; g_rowptr[0] = 0; }
    __syncthreads();
    for (int base = 0; base < NN; base += 1024) {
        int i = base + threadIdx.x;
        int v = (i < NN) ? g_deg[i] : 0;
        sm[threadIdx.x] = v;
        __syncthreads();
        for (int off = 1; off < 1024; off <<= 1) {
            int t = (threadIdx.x >= off) ? sm[threadIdx.x - off] : 0;
            __syncthreads();
            sm[threadIdx.x] += t;
            __syncthreads();
        }
        if (i < NN) g_rowptr[i + 1] = carry + sm[threadIdx.x];
        __syncthreads();
        if (threadIdx.x == 0) carry += sm[1023];
        __syncthreads();
    }
    for (int i = threadIdx.x; i < NN; i += 1024) g_cursor[i] = g_rowptr[i];
}

__global__ void k_fill(const void* __restrict__ ei, int E) {
    int e = blockIdx.x * blockDim.x + threadIdx.x;
    if (e < E) {
        int dst = edge_at(ei, E, (long long)E + e);
        int src = edge_at(ei, E, e);
        if ((unsigned)dst < NN && (unsigned)src < NN) {
            int pos = atomicAdd(&g_cursor[dst], 1);
            if ((unsigned)pos < MAXE) g_colidx[pos] = src;
        }
    }
}

// zero gap/pad strips of layer-2 A layout (cols 250,251,502,503,754..767)
__global__ void k_zp2() {
    long long idx = (long long)blockIdx.x * blockDim.x + threadIdx.x;
    if (idx >= (long long)NN * 18) return;
    int row = (int)(idx / 18);
    int j = (int)(idx % 18);
    int col = (j < 2) ? 250 + j : (j < 4 ? 500 + j : 750 + j);
    size_t o = (size_t)row * 768 + col;
    g_Ahi[o] = __float2half(0.0f);
    g_Alo[o] = __float2half(0.0f);
}
// zero pad of layer-3 A layout (cols 1500..1535)
__global__ void k_zp3() {
    long long idx = (long long)blockIdx.x * blockDim.x + threadIdx.x;
    if (idx >= (long long)NN * 36) return;
    int row = (int)(idx / 36);
    int col = 1500 + (int)(idx % 36);
    size_t o = (size_t)row * 1536 + col;
    g_Ahi[o] = __float2half(0.0f);
    g_Alo[o] = __float2half(0.0f);
}

// ---------------- SpMM (warp per dst row, CSR; float2 lanes) ----------------
// out = mul*(diag[row]*in[row] - dis[row]*sum(dis[s]*in[s])) + subcoef*sub[row]
// (+bias, relu).  If astr != 0: also write fp16 hi/lo of result into
// g_Ahi/g_Alo at [row*astr + aoff + f].
template <int F>
__global__ void k_spmm2(const float* __restrict__ ext,
                        int sel_in, int off_in, int str_in,
                        int sel_sub, int off_sub, int str_sub,
                        int sel_out, int str_out,
                        float mul, float subcoef,
                        const float* __restrict__ bias, int do_relu,
                        int aoff, int astr) {
    constexpr int NH = F / 2;
    constexpr int NR = (NH + 31) / 32;
    const float* hin  = selbuf(sel_in, ext) + off_in;
    const float* hsub = selbuf(sel_sub, ext) + off_sub;
    float* out = selbuf_mut(sel_out, nullptr);

    int warp = (blockIdx.x * blockDim.x + threadIdx.x) >> 5;
    int lane = threadIdx.x & 31;
    if (warp >= NN) return;
    int row = warp;
    int s = g_rowptr[row], e = g_rowptr[row + 1];

    float2 acc[NR];
#pragma unroll
    for (int r = 0; r < NR; r++) acc[r] = make_float2(0.f, 0.f);

    for (int j = s; j < e; j++) {
        int src = g_colidx[j];
        float ws = g_dis[src];
        const float2* hp = (const float2*)(hin + (size_t)src * str_in);
#pragma unroll
        for (int r = 0; r < NR; r++) {
            int f2 = lane + r * 32;
            if ((NH & 31) == 0 || f2 < NH) {
                float2 v = hp[f2];
                acc[r].x += ws * v.x;
                acc[r].y += ws * v.y;
            }
        }
    }

    float di = g_dis[row], dg = g_diag[row];
    const float2* hr = (const float2*)(hin + (size_t)row * str_in);
    const float2* sr = (const float2*)(hsub + (size_t)row * str_sub);
    float2* orow = (float2*)(out + (size_t)row * str_out);
    uint32_t* ahr = astr ? (uint32_t*)(g_Ahi + (size_t)row * astr + aoff) : nullptr;
    uint32_t* alr = astr ? (uint32_t*)(g_Alo + (size_t)row * astr + aoff) : nullptr;
#pragma unroll
    for (int r = 0; r < NR; r++) {
        int f2 = lane + r * 32;
        if ((NH & 31) == 0 || f2 < NH) {
            float2 h = hr[f2];
            float vx = mul * (dg * h.x - di * acc[r].x);
            float vy = mul * (dg * h.y - di * acc[r].y);
            if (subcoef != 0.0f) {
                float2 sv = sr[f2];
                vx += subcoef * sv.x;
                vy += subcoef * sv.y;
            }
            if (bias) {
                vx += bias[2 * f2];
                vy += bias[2 * f2 + 1];
            }
            if (do_relu) {
                vx = vx > 0.f ? vx : 0.f;
                vy = vy > 0.f ? vy : 0.f;
            }
            orow[f2] = make_float2(vx, vy);
            if (astr) {
                uint32_t hp2 = pack_hi2(vx, vy);
                ahr[f2] = hp2;
                alr[f2] = pack_lo2(vx, vy, hp2);
            }
        }
    }
}

// ---------------- fp16 conversion kernels ------------------------------------
// layer-1 A: x fp32 [NN,512] -> hi/lo [NN,512]
__global__ void k_cvtA1(const float* __restrict__ x) {
    long long idx = (long long)blockIdx.x * blockDim.x + threadIdx.x;
    if (idx >= (long long)NN * 512) return;
    float v = x[idx];
    __half hi = __float2half(v);
    g_Ahi[idx] = hi;
    g_Alo[idx] = __float2half(v - __half2float(hi));
}

// layer-3 A block 0: h2 [NN,500] -> hi/lo at [m*1536 + k], k<500
__global__ void k_cvtA3(void) {
    long long idx = (long long)blockIdx.x * blockDim.x + threadIdx.x;
    if (idx >= (long long)NN * 500) return;
    int m = (int)(idx / 500);
    int k = (int)(idx % 500);
    float v = g_h2[(size_t)m * 500 + k];
    __half hi = __float2half(v);
    size_t o = (size_t)m * 1536 + k;
    g_Ahi[o] = hi;
    g_Alo[o] = __float2half(v - __half2float(hi));
}

// generic W: fp32 [3K,N] -> transposed fp16 [Npad,Kpad] (layer 3)
__global__ void k_cvtW(const float* __restrict__ W, int K, int N, int Npad, int Kpad) {
    long long idx = (long long)blockIdx.x * blockDim.x + threadIdx.x;
    long long total = (long long)Npad * Kpad;
    if (idx >= total) return;
    int kk = (int)(idx % Kpad);
    int n  = (int)(idx / Kpad);
    float v = (n < N && kk < 3 * K) ? W[(size_t)kk * N + n] : 0.0f;
    g_Wt[idx] = __float2half(v);
}

// layer-1 combined weights: rows n in [0,768): b=n>>8, nn=n&255.
// b0: W0-W2, b1: W1, b2: W2 (w layout [3,512,250]); cols k in [0,512).
__global__ void k_cvtW1(const float* __restrict__ w) {
    long long idx = (long long)blockIdx.x * blockDim.x + threadIdx.x;
    if (idx >= 768LL * 512) return;
    int k = (int)(idx & 511);
    int n = (int)(idx >> 9);
    int b = n >> 8, nn = n & 255;
    float v = 0.0f;
    if (nn < 250) {
        if (b == 0)
            v = w[(size_t)k * 250 + nn] - w[2 * 512 * 250 + (size_t)k * 250 + nn];
        else
            v = w[(size_t)b * 512 * 250 + (size_t)k * 250 + nn];
    }
    g_Wt[idx] = __float2half(v);
}

// layer-2 W with gap-aligned k mapping: kk in [0,250)->k3=kk;
// [252,502)->k3=kk-2; [504,754)->k3=kk-4; else 0. (w2 = [750,500] row-major)
__global__ void k_cvtW2(const float* __restrict__ w) {
    long long idx = (long long)blockIdx.x * blockDim.x + threadIdx.x;
    if (idx >= 512LL * 768) return;
    int kk = (int)(idx % 768);
    int n  = (int)(idx / 768);
    float v = 0.0f;
    if (n < 500) {
        int k3 = -1;
        if (kk < 250) k3 = kk;
        else if (kk >= 252 && kk < 502) k3 = kk - 2;
        else if (kk >= 504 && kk < 754) k3 = kk - 4;
        if (k3 >= 0) v = w[(size_t)k3 * 500 + n];
    }
    g_Wt[idx] = __float2half(v);
}

// ---------------- mma.sync GEMM, cp.async double-buffered, fp16 2-term ------
// C = (Ahi + Alo) · Wt^T  (+bias, relu if bias != nullptr)
#define TBM 128
#define TBN 128
#define TBK 32
#define SROW 40
#define OFF_AH 0
#define OFF_AL (TBM * SROW * 2)
#define OFF_B  (2 * TBM * SROW * 2)
#define STAGE_BYTES ((2 * TBM + TBN) * SROW * 2)   // 30720
#define SMEM_TOTAL (2 * STAGE_BYTES)               // 61440

__global__ void __launch_bounds__(256, 2) k_mmagemm(
    const float* __restrict__ bias, float* __restrict__ extC, int selC,
    int M, int N, int Kpad) {
    extern __shared__ __align__(16) char dynsm[];
    const uint32_t sbase = smem_to_u32(dynsm);

    float* C = selbuf_mut(selC, extC);
    const int tid = threadIdx.x;
    const int wid = tid >> 5, lane = tid & 31;
    const int wm = wid >> 1, wn = wid & 1;
    const int blockM = blockIdx.y * TBM;
    const int blockN = blockIdx.x * TBN;

    const int ldrow = tid >> 2;
    const int ldcol = (tid & 3) * 8;
    const int nch = Kpad / TBK;

    auto prefetch = [&](int kc, int st) {
        uint32_t sb = sbase + st * STAGE_BYTES;
#pragma unroll
        for (int p = 0; p < 2; p++) {
            int row = ldrow + p * 64;
            uint32_t dsto = (uint32_t)(row * SROW + ldcol) * 2;
            int gA = blockM + row;
            int okA = (gA < M) ? 16 : 0;
            size_t aoff = (size_t)gA * Kpad + kc * TBK + ldcol;
            cp16(sb + OFF_AH + dsto, g_Ahi + aoff, okA);
            cp16(sb + OFF_AL + dsto, g_Alo + aoff, okA);
            size_t boff = (size_t)(blockN + row) * Kpad + kc * TBK + ldcol;
            cp16(sb + OFF_B + dsto, g_Wt + boff, 16);
        }
    };

    float acc[2][8][4];
#pragma unroll
    for (int i = 0; i < 2; i++)
#pragma unroll
        for (int j = 0; j < 8; j++)
#pragma unroll
            for (int q = 0; q < 4; q++) acc[i][j][q] = 0.0f;

    prefetch(0, 0);
    CP_COMMIT();

    for (int kc = 0; kc < nch; kc++) {
        int st = kc & 1;
        if (kc + 1 < nch) {
            prefetch(kc + 1, st ^ 1);
            CP_COMMIT();
            CP_WAIT1();
        } else {
            CP_WAIT0();
        }
        __syncthreads();

        uint32_t sb = sbase + st * STAGE_BYTES;
        uint32_t uAh = sb + OFF_AH, uAl = sb + OFF_AL, uB = sb + OFF_B;

#pragma unroll
        for (int ks = 0; ks < TBK; ks += 16) {
            uint32_t Ah[2][4], Al[2][4];
            {
                int arow = wm * 32 + (lane & 15);
                int akof = ks + ((lane >> 4) * 8);
#pragma unroll
                for (int mi = 0; mi < 2; mi++) {
                    uint32_t off = (uint32_t)((arow + mi * 16) * SROW + akof) * 2;
                    ldsm4(Ah[mi], uAh + off);
                    ldsm4(Al[mi], uAl + off);
                }
            }
            uint32_t Bf[8][2];
            {
                int bn = wn * 64 + ((lane >> 4) * 8) + (lane & 7);
                int bk = ks + (((lane >> 3) & 1) * 8);
#pragma unroll
                for (int np = 0; np < 4; np++) {
                    uint32_t off = (uint32_t)((bn + np * 16) * SROW + bk) * 2;
                    uint32_t rh[4];
                    ldsm4(rh, uB + off);
                    Bf[np * 2][0] = rh[0]; Bf[np * 2][1] = rh[1];
                    Bf[np * 2 + 1][0] = rh[2]; Bf[np * 2 + 1][1] = rh[3];
                }
            }
#pragma unroll
            for (int mi = 0; mi < 2; mi++)
#pragma unroll
                for (int ni = 0; ni < 8; ni++) {
                    mma_f16(acc[mi][ni], Ah[mi], Bf[ni]);
                    mma_f16(acc[mi][ni], Al[mi], Bf[ni]);
                }
        }
        __syncthreads();
    }

    // ---- epilogue
    const int g = lane >> 2, t = lane & 3;
#pragma unroll
    for (int mi = 0; mi < 2; mi++) {
        int r0 = blockM + wm * 32 + mi * 16 + g;
#pragma unroll
        for (int ni = 0; ni < 8; ni++) {
            int c0 = blockN + wn * 64 + ni * 8 + 2 * t;
            if (c0 >= N) continue;
            bool c1ok = (c0 + 1) < N;
            float bv0 = bias ? bias[c0] : 0.0f;
            float bv1 = (bias && c1ok) ? bias[c0 + 1] : 0.0f;
            if (r0 < M) {
                float v0 = acc[mi][ni][0] + bv0;
                if (bias) v0 = v0 > 0.f ? v0 : 0.f;
                C[(size_t)r0 * N + c0] = v0;
                if (c1ok) {
                    float v1 = acc[mi][ni][1] + bv1;
                    if (bias) v1 = v1 > 0.f ? v1 : 0.f;
                    C[(size_t)r0 * N + c0 + 1] = v1;
                }
            }
            if (r0 + 8 < M) {
                float v2 = acc[mi][ni][2] + bv0;
                if (bias) v2 = v2 > 0.f ? v2 : 0.f;
                C[(size_t)(r0 + 8) * N + c0] = v2;
                if (c1ok) {
                    float v3 = acc[mi][ni][3] + bv1;
                    if (bias) v3 = v3 > 0.f ? v3 : 0.f;
                    C[(size_t)(r0 + 8) * N + c0 + 1] = v3;
                }
            }
        }
    }
}

// ---------------- orchestration ---------------------------------------------
extern "C" void kernel_launch(void* const* d_in, const int* in_sizes, int n_in,
                              void* d_out, int out_size) {
    const float* x  = (const float*)d_in[0];
    const void*  ei = d_in[1];
    const float* w1 = (const float*)d_in[2];
    const float* b1 = (const float*)d_in[3];
    const float* w2 = (const float*)d_in[4];
    const float* b2 = (const float*)d_in[5];
    const float* w3 = (const float*)d_in[6];
    const float* b3 = (const float*)d_in[7];
    float* out = (float*)d_out;
    int E = in_sizes[1] / 2;

    cudaFuncSetAttribute(k_mmagemm, cudaFuncAttributeMaxDynamicSharedMemorySize,
                         SMEM_TOTAL);

    int nb = (NN + 255) / 256;
    int eb = (E + 255) / 256;
    int spb = (NN * 32 + 255) / 256;
    int mt = (NN + TBM - 1) / TBM;   // 391

    // (1) layer-1 A convert    (2) layer-1 W convert
    k_cvtA1<<<(unsigned)(((long long)NN * 512 + 255) / 256), 256>>>(x);
    k_cvtW1<<<(unsigned)((768LL * 512 + 255) / 256), 256>>>(w1);
    // (3) detect + zero degree
    k_dzero<<<nb, 256>>>((const int*)ei);
    // (4) layer-1 GEMM: U = x @ [W0-W2 | W1 | W2]^T  -> g_u [NN,768]
    {
        dim3 g(768 / TBN, mt);
        k_mmagemm<<<g, 256, SMEM_TOTAL>>>(nullptr, nullptr, 5, NN, 768, 512);
    }
    // (5..8) graph prep + layer-2 A gap zeroing
    k_count<<<eb, 256>>>(ei, E);
    k_dsc<<<1, 1024>>>();
    k_fill<<<eb, 256>>>(ei, E);
    k_zp2<<<(unsigned)(((long long)NN * 18 + 255) / 256), 256>>>();

    // (9) v = u1 + 2*Lhat(u2)  -> tx1 (str 250)
    k_spmm2<250><<<spb, 256>>>(nullptr, 5, 512, 768, 5, 256, 768, 1, 250,
                               2.0f, 1.0f, nullptr, 0, 0, 0);
    // (10) h1 = relu(u0 + Lhat(v) + b1) -> h1 + A2-block0
    k_spmm2<250><<<spb, 256>>>(nullptr, 1, 0, 250, 5, 0, 768, 3, 250,
                               1.0f, 1.0f, b1, 1, 0, 768);
    // (11) tx1 = Lhat(h1) + A2-block1 @252
    k_spmm2<250><<<spb, 256>>>(nullptr, 3, 0, 250, 3, 0, 250, 1, 250,
                               1.0f, 0.0f, nullptr, 0, 252, 768);
    // (12) tx2 = 2*Lhat(tx1) - h1 + A2-block2 @504
    k_spmm2<250><<<spb, 256>>>(nullptr, 1, 0, 250, 3, 0, 250, 2, 250,
                               2.0f, -1.0f, nullptr, 0, 504, 768);
    // (13) layer-2 W convert, (14) layer-2 GEMM -> h2 [NN,500]
    k_cvtW2<<<(unsigned)((512LL * 768 + 255) / 256), 256>>>(w2);
    {
        dim3 g(512 / TBN, mt);
        k_mmagemm<<<g, 256, SMEM_TOTAL>>>(b2, nullptr, 4, NN, 500, 768);
    }
    // (15) layer-3 pad zeroing, (16) h2 -> A3-block0
    k_zp3<<<(unsigned)(((long long)NN * 36 + 255) / 256), 256>>>();
    k_cvtA3<<<(unsigned)(((long long)NN * 500 + 255) / 256), 256>>>();
    // (17) tx1 = Lhat(h2) + A3-block1 @500
    k_spmm2<500><<<spb, 256>>>(nullptr, 4, 0, 500, 4, 0, 500, 1, 500,
                               1.0f, 0.0f, nullptr, 0, 500, 1536);
    // (18) tx2 = 2*Lhat(tx1) - h2 + A3-block2 @1000
    k_spmm2<500><<<spb, 256>>>(nullptr, 1, 0, 500, 4, 0, 500, 2, 500,
                               2.0f, -1.0f, nullptr, 0, 1000, 1536);
    // (19) layer-3 W convert, (20) layer-3 GEMM -> out
    {
        long long tW = 1024LL * 1536;
        k_cvtW<<<(unsigned)((tW + 255) / 256), 256>>>(w3, 500, 1000, 1024, 1536);
        dim3 g(1024 / TBN, mt);
        k_mmagemm<<<g, 256, SMEM_TOTAL>>>(b3, out, 0, NN, 1000, 1536);
    }
}

// round 16
// speedup vs baseline: 2.5084x; 1.1484x over previous
#include <cuda_runtime.h>
#include <cuda_fp16.h>
#include <cstdint>

#define NN 50000
#define MAXE 1600000
#define KPADMAX 1536

// ---------------- scratch (static device globals) ---------------------------
__device__ __align__(16) float g_tx1[NN * 512];
__device__ __align__(16) float g_tx2[NN * 512];
__device__ __align__(16) float g_h1 [NN * 252];   // stride 250 used
__device__ __align__(16) float g_h2 [NN * 500];
__device__ __align__(16) float g_u  [NN * 768];   // layer-1 GEMM out [u0|u1|u2]
__device__ __align__(16) __half g_Ahi[(size_t)NN * KPADMAX];
__device__ __align__(16) __half g_Alo[(size_t)NN * KPADMAX];
__device__ __align__(16) __half g_Wt [1024 * KPADMAX];
__device__ int   g_deg[NN];
__device__ int   g_rowptr[NN + 1];
__device__ int   g_cursor[NN];
__device__ int   g_colidx[MAXE];
__device__ float g_dis[NN];
__device__ float g_diag[NN];
__device__ int   g_is64;

// fp16 stash regions inside g_Ahi's upper half (element offsets):
#define SB_U2 ((long long)NN * 768)    // u2-hi, stride 256
#define SB_V  ((long long)NN * 1024)   // v-hi,  stride 256

__device__ __forceinline__ const float* selbuf(int sel, const float* ext) {
    switch (sel) {
        case 1: return g_tx1;
        case 2: return g_tx2;
        case 3: return g_h1;
        case 4: return g_h2;
        case 5: return g_u;
        default: return ext;
    }
}
__device__ __forceinline__ float* selbuf_mut(int sel, float* ext) {
    switch (sel) {
        case 1: return g_tx1;
        case 2: return g_tx2;
        case 3: return g_h1;
        case 4: return g_h2;
        case 5: return g_u;
        default: return ext;
    }
}

__device__ __forceinline__ int edge_at(const void* ei, int E, long long idx) {
    if (g_is64) return (int)((const long long*)ei)[idx];
    return ((const int*)ei)[idx];
}

__device__ __forceinline__ uint32_t smem_to_u32(const void* p) {
    uint32_t a;
    asm("{ .reg .u64 t; cvta.to.shared.u64 t, %1; cvt.u32.u64 %0, t; }"
        : "=r"(a) : "l"(p));
    return a;
}

// mma.sync fp16 (sm_80 path; legal on plain sm_103 target)
__device__ __forceinline__ void mma_f16(float* c, const uint32_t* a, const uint32_t* b) {
    asm volatile("mma.sync.aligned.m16n8k16.row.col.f32.f16.f16.f32 "
        "{%0,%1,%2,%3}, {%4,%5,%6,%7}, {%8,%9}, {%0,%1,%2,%3};"
        : "+f"(c[0]), "+f"(c[1]), "+f"(c[2]), "+f"(c[3])
        : "r"(a[0]), "r"(a[1]), "r"(a[2]), "r"(a[3]), "r"(b[0]), "r"(b[1]));
}
__device__ __forceinline__ void ldsm4(uint32_t* r, uint32_t addr) {
    asm volatile("ldmatrix.sync.aligned.m8n8.x4.shared.b16 {%0,%1,%2,%3}, [%4];"
        : "=r"(r[0]), "=r"(r[1]), "=r"(r[2]), "=r"(r[3]) : "r"(addr));
}
__device__ __forceinline__ void cp16(uint32_t dst, const void* src, int src_bytes) {
    asm volatile("cp.async.cg.shared.global [%0], [%1], 16, %2;"
                 :: "r"(dst), "l"(src), "r"(src_bytes));
}
#define CP_COMMIT() asm volatile("cp.async.commit_group;" ::: "memory")
#define CP_WAIT2()  asm volatile("cp.async.wait_group 2;" ::: "memory")
#define CP_WAIT1()  asm volatile("cp.async.wait_group 1;" ::: "memory")
#define CP_WAIT0()  asm volatile("cp.async.wait_group 0;" ::: "memory")

__device__ __forceinline__ uint32_t pack_hi2(float x, float y) {
    __half2 h;
    h.x = __float2half(x);
    h.y = __float2half(y);
    return *(const uint32_t*)&h;
}
__device__ __forceinline__ uint32_t pack_lo2(float x, float y, uint32_t hi) {
    const __half2* hp = (const __half2*)&hi;
    __half2 l;
    l.x = __float2half(x - __half2float(hp->x));
    l.y = __float2half(y - __half2float(hp->y));
    return *(const uint32_t*)&l;
}

// ---------------- prep kernels ----------------------------------------------
__global__ void k_dzero(const int* __restrict__ ei32) {
    int i = blockIdx.x * blockDim.x + threadIdx.x;
    if (i < NN) g_deg[i] = 0;
    if (blockIdx.x == 0 && threadIdx.x == 0) {
        int all0 = 1;
        for (int q = 0; q < 64; q++)
            if (ei32[2 * q + 1] != 0) { all0 = 0; break; }
        g_is64 = all0;
    }
}

__global__ void k_count(const void* __restrict__ ei, int E) {
    int e = blockIdx.x * blockDim.x + threadIdx.x;
    if (e < E) {
        int dst = edge_at(ei, E, (long long)E + e);
        if ((unsigned)dst < NN) atomicAdd(&g_deg[dst], 1);
    }
}

// dis + single-block scan + cursor (fused)
__global__ void k_dsc() {
    for (int i = threadIdx.x; i < NN; i += 1024) {
        int d = g_deg[i];
        g_dis[i]  = d > 0 ? rsqrtf((float)d) : 0.0f;
        g_diag[i] = d > 0 ? 0.0f : -1.0f;
    }
    __shared__ int sm[1024];
    __shared__ int carry;
    if (threadIdx.x == 0) { carry = 0; g_rowptr[0] = 0; }
    __syncthreads();
    for (int base = 0; base < NN; base += 1024) {
        int i = base + threadIdx.x;
        int v = (i < NN) ? g_deg[i] : 0;
        sm[threadIdx.x] = v;
        __syncthreads();
        for (int off = 1; off < 1024; off <<= 1) {
            int t = (threadIdx.x >= off) ? sm[threadIdx.x - off] : 0;
            __syncthreads();
            sm[threadIdx.x] += t;
            __syncthreads();
        }
        if (i < NN) g_rowptr[i + 1] = carry + sm[threadIdx.x];
        __syncthreads();
        if (threadIdx.x == 0) carry += sm[1023];
        __syncthreads();
    }
    for (int i = threadIdx.x; i < NN; i += 1024) g_cursor[i] = g_rowptr[i];
}

__global__ void k_fill(const void* __restrict__ ei, int E) {
    int e = blockIdx.x * blockDim.x + threadIdx.x;
    if (e < E) {
        int dst = edge_at(ei, E, (long long)E + e);
        int src = edge_at(ei, E, e);
        if ((unsigned)dst < NN && (unsigned)src < NN) {
            int pos = atomicAdd(&g_cursor[dst], 1);
            if ((unsigned)pos < MAXE) g_colidx[pos] = src;
        }
    }
}

// zero gap/pad strips of layer-2 A layout (cols 250,251,502,503,754..767)
__global__ void k_zp2() {
    long long idx = (long long)blockIdx.x * blockDim.x + threadIdx.x;
    if (idx >= (long long)NN * 18) return;
    int row = (int)(idx / 18);
    int j = (int)(idx % 18);
    int col = (j < 2) ? 250 + j : (j < 4 ? 500 + j : 750 + j);
    size_t o = (size_t)row * 768 + col;
    g_Ahi[o] = __float2half(0.0f);
    g_Alo[o] = __float2half(0.0f);
}
// zero pad of layer-3 A layout (cols 1500..1535)
__global__ void k_zp3() {
    long long idx = (long long)blockIdx.x * blockDim.x + threadIdx.x;
    if (idx >= (long long)NN * 36) return;
    int row = (int)(idx / 36);
    int col = 1500 + (int)(idx % 36);
    size_t o = (size_t)row * 1536 + col;
    g_Ahi[o] = __float2half(0.0f);
    g_Alo[o] = __float2half(0.0f);
}

// u2 (g_u cols 512..761) -> fp16 stash at SB_U2 (stride 256)
__global__ void k_cvtU() {
    long long idx = (long long)blockIdx.x * blockDim.x + threadIdx.x;
    if (idx >= (long long)NN * 250) return;
    int m = (int)(idx / 250);
    int k = (int)(idx % 250);
    float v = g_u[(size_t)m * 768 + 512 + k];
    g_Ahi[SB_U2 + (size_t)m * 256 + k] = __float2half(v);
}

// ---------------- SpMM: fp16 gather, fp32 row-local (warp per dst row) ------
// out = mul*(diag[row]*in[row] - dis[row]*sum(dis[s]*ghi[s])) + subcoef*sub[row]
// (+bias, relu). ghi = fp16 plane in g_Ahi at (goff, gstr).
// If astr: write fp16 hi/lo of result into g_Ahi/g_Alo at (aoff, astr).
// If mstr: also write fp16 hi into g_Ahi at (moff, mstr).
template <int F>
__global__ void k_spmmh(long long goff, int gstr,
                        const float* __restrict__ ext, int rsel, int roff, int rstr,
                        int ssel, int soff, int sstr,
                        int osel, int ostr,
                        float mul, float subcoef,
                        const float* __restrict__ bias, int do_relu,
                        int aoff, int astr, long long moff, int mstr) {
    constexpr int NC = (F + 3) / 4;          // 4-feature chunks
    constexpr int NRr = (NC + 31) / 32;
    const __half* g = g_Ahi + goff;
    const float* hrow = selbuf(rsel, ext) + roff;
    const float* hsub = selbuf(ssel, ext) + soff;
    float* out = selbuf_mut(osel, nullptr);

    int warp = (blockIdx.x * blockDim.x + threadIdx.x) >> 5;
    int lane = threadIdx.x & 31;
    if (warp >= NN) return;
    int row = warp;
    int s = g_rowptr[row], e = g_rowptr[row + 1];

    float4 acc[NRr];
#pragma unroll
    for (int r = 0; r < NRr; r++) acc[r] = make_float4(0.f, 0.f, 0.f, 0.f);

    for (int j = s; j < e; j++) {
        int src = g_colidx[j];
        float ws = g_dis[src];
        const uint2* gp = (const uint2*)(g + (size_t)src * gstr);
#pragma unroll
        for (int r = 0; r < NRr; r++) {
            int c = lane + r * 32;
            if ((NC & 31) == 0 || c < NC) {
                uint2 v = gp[c];
                float2 f0 = __half22float2(*(const __half2*)&v.x);
                float2 f1 = __half22float2(*(const __half2*)&v.y);
                acc[r].x += ws * f0.x; acc[r].y += ws * f0.y;
                acc[r].z += ws * f1.x; acc[r].w += ws * f1.y;
            }
        }
    }

    float di = g_dis[row], dg = g_diag[row];
    const float* hr = hrow + (size_t)row * rstr;
    const float* sr = hsub + (size_t)row * sstr;
    float* orow = out + (size_t)row * ostr;
    uint32_t* ahr = astr ? (uint32_t*)(g_Ahi + (size_t)row * astr + aoff) : nullptr;
    uint32_t* alr = astr ? (uint32_t*)(g_Alo + (size_t)row * astr + aoff) : nullptr;
    uint32_t* mhr = mstr ? (uint32_t*)(g_Ahi + moff + (size_t)row * mstr) : nullptr;

#pragma unroll
    for (int r = 0; r < NRr; r++) {
        int c = lane + r * 32;
        if ((NC & 31) != 0 && c >= NC) continue;
        int base = 4 * c;
        float a[4] = {acc[r].x, acc[r].y, acc[r].z, acc[r].w};
        float vv[4];
#pragma unroll
        for (int q = 0; q < 4; q++) {
            int idx = base + q;
            if ((F & 3) == 0 || idx < F) {
                float v = mul * (dg * hr[idx] - di * a[q]);
                if (subcoef != 0.0f) v += subcoef * sr[idx];
                if (bias) v += bias[idx];
                if (do_relu) v = v > 0.f ? v : 0.f;
                orow[idx] = v;
                vv[q] = v;
            } else {
                vv[q] = 0.0f;
            }
        }
#pragma unroll
        for (int p = 0; p < 2; p++) {
            int idx = base + 2 * p;
            if ((F & 3) == 0 || idx < F) {       // F even -> pair fully valid
                if (astr) {
                    uint32_t h2 = pack_hi2(vv[2 * p], vv[2 * p + 1]);
                    ahr[2 * c + p] = h2;
                    alr[2 * c + p] = pack_lo2(vv[2 * p], vv[2 * p + 1], h2);
                }
                if (mstr) mhr[2 * c + p] = pack_hi2(vv[2 * p], vv[2 * p + 1]);
            }
        }
    }
}

// ---------------- fp16 conversion kernels ------------------------------------
// layer-1 A: x fp32 [NN,512] -> hi/lo [NN,512]
__global__ void k_cvtA1(const float* __restrict__ x) {
    long long idx = (long long)blockIdx.x * blockDim.x + threadIdx.x;
    if (idx >= (long long)NN * 512) return;
    float v = x[idx];
    __half hi = __float2half(v);
    g_Ahi[idx] = hi;
    g_Alo[idx] = __float2half(v - __half2float(hi));
}

// layer-3 A block 0: h2 [NN,500] -> hi/lo at [m*1536 + k], k<500
__global__ void k_cvtA3(void) {
    long long idx = (long long)blockIdx.x * blockDim.x + threadIdx.x;
    if (idx >= (long long)NN * 500) return;
    int m = (int)(idx / 500);
    int k = (int)(idx % 500);
    float v = g_h2[(size_t)m * 500 + k];
    __half hi = __float2half(v);
    size_t o = (size_t)m * 1536 + k;
    g_Ahi[o] = hi;
    g_Alo[o] = __float2half(v - __half2float(hi));
}

// generic W: fp32 [3K,N] -> transposed fp16 [Npad,Kpad] (layer 3)
__global__ void k_cvtW(const float* __restrict__ W, int K, int N, int Npad, int Kpad) {
    long long idx = (long long)blockIdx.x * blockDim.x + threadIdx.x;
    long long total = (long long)Npad * Kpad;
    if (idx >= total) return;
    int kk = (int)(idx % Kpad);
    int n  = (int)(idx / Kpad);
    float v = (n < N && kk < 3 * K) ? W[(size_t)kk * N + n] : 0.0f;
    g_Wt[idx] = __float2half(v);
}

// layer-1 combined weights (w layout [3,512,250])
__global__ void k_cvtW1(const float* __restrict__ w) {
    long long idx = (long long)blockIdx.x * blockDim.x + threadIdx.x;
    if (idx >= 768LL * 512) return;
    int k = (int)(idx & 511);
    int n = (int)(idx >> 9);
    int b = n >> 8, nn = n & 255;
    float v = 0.0f;
    if (nn < 250) {
        if (b == 0)
            v = w[(size_t)k * 250 + nn] - w[2 * 512 * 250 + (size_t)k * 250 + nn];
        else
            v = w[(size_t)b * 512 * 250 + (size_t)k * 250 + nn];
    }
    g_Wt[idx] = __float2half(v);
}

// layer-2 W, gap-aligned k mapping (w2 = [750,500] row-major)
__global__ void k_cvtW2(const float* __restrict__ w) {
    long long idx = (long long)blockIdx.x * blockDim.x + threadIdx.x;
    if (idx >= 512LL * 768) return;
    int kk = (int)(idx % 768);
    int n  = (int)(idx / 768);
    float v = 0.0f;
    if (n < 500) {
        int k3 = -1;
        if (kk < 250) k3 = kk;
        else if (kk >= 252 && kk < 502) k3 = kk - 2;
        else if (kk >= 504 && kk < 754) k3 = kk - 4;
        if (k3 >= 0) v = w[(size_t)k3 * 500 + n];
    }
    g_Wt[idx] = __float2half(v);
}

// ---------------- mma.sync GEMM, cp.async 3-stage, fp16 2-term ---------------
// C = (Ahi + Alo) · Wt^T  (+bias, relu if bias != nullptr)
#define TBM 128
#define TBN 128
#define TBK 32
#define SROW 40
#define OFF_AH 0
#define OFF_AL (TBM * SROW * 2)
#define OFF_B  (2 * TBM * SROW * 2)
#define STAGE_BYTES ((2 * TBM + TBN) * SROW * 2)   // 30720
#define NSTAGE 3
#define SMEM_TOTAL (NSTAGE * STAGE_BYTES)          // 92160 -> 2 CTAs still fit

__global__ void __launch_bounds__(256, 2) k_mmagemm(
    const float* __restrict__ bias, float* __restrict__ extC, int selC,
    int M, int N, int Kpad) {
    extern __shared__ __align__(16) char dynsm[];
    const uint32_t sbase = smem_to_u32(dynsm);

    float* C = selbuf_mut(selC, extC);
    const int tid = threadIdx.x;
    const int wid = tid >> 5, lane = tid & 31;
    const int wm = wid >> 1, wn = wid & 1;
    const int blockM = blockIdx.y * TBM;
    const int blockN = blockIdx.x * TBN;

    const int ldrow = tid >> 2;
    const int ldcol = (tid & 3) * 8;
    const int nch = Kpad / TBK;

    auto prefetch = [&](int kc, int st) {
        uint32_t sb = sbase + st * STAGE_BYTES;
#pragma unroll
        for (int p = 0; p < 2; p++) {
            int row = ldrow + p * 64;
            uint32_t dsto = (uint32_t)(row * SROW + ldcol) * 2;
            int gA = blockM + row;
            int okA = (gA < M) ? 16 : 0;
            size_t aoff = (size_t)gA * Kpad + kc * TBK + ldcol;
            cp16(sb + OFF_AH + dsto, g_Ahi + aoff, okA);
            cp16(sb + OFF_AL + dsto, g_Alo + aoff, okA);
            size_t boff = (size_t)(blockN + row) * Kpad + kc * TBK + ldcol;
            cp16(sb + OFF_B + dsto, g_Wt + boff, 16);
        }
    };

    float acc[2][8][4];
#pragma unroll
    for (int i = 0; i < 2; i++)
#pragma unroll
        for (int j = 0; j < 8; j++)
#pragma unroll
            for (int q = 0; q < 4; q++) acc[i][j][q] = 0.0f;

    prefetch(0, 0);
    CP_COMMIT();
    if (nch > 1) { prefetch(1, 1); CP_COMMIT(); }

    int st = 0;
    for (int kc = 0; kc < nch; kc++) {
        if (kc + 2 < nch) {
            int st2 = st + 2; if (st2 >= NSTAGE) st2 -= NSTAGE;
            prefetch(kc + 2, st2);
            CP_COMMIT();
            CP_WAIT2();
        } else if (kc + 1 < nch) {
            CP_WAIT1();
        } else {
            CP_WAIT0();
        }
        __syncthreads();

        uint32_t sb = sbase + st * STAGE_BYTES;
        uint32_t uAh = sb + OFF_AH, uAl = sb + OFF_AL, uB = sb + OFF_B;

#pragma unroll
        for (int ks = 0; ks < TBK; ks += 16) {
            uint32_t Ah[2][4], Al[2][4];
            {
                int arow = wm * 32 + (lane & 15);
                int akof = ks + ((lane >> 4) * 8);
#pragma unroll
                for (int mi = 0; mi < 2; mi++) {
                    uint32_t off = (uint32_t)((arow + mi * 16) * SROW + akof) * 2;
                    ldsm4(Ah[mi], uAh + off);
                    ldsm4(Al[mi], uAl + off);
                }
            }
            uint32_t Bf[8][2];
            {
                int bn = wn * 64 + ((lane >> 4) * 8) + (lane & 7);
                int bk = ks + (((lane >> 3) & 1) * 8);
#pragma unroll
                for (int np = 0; np < 4; np++) {
                    uint32_t off = (uint32_t)((bn + np * 16) * SROW + bk) * 2;
                    uint32_t rh[4];
                    ldsm4(rh, uB + off);
                    Bf[np * 2][0] = rh[0]; Bf[np * 2][1] = rh[1];
                    Bf[np * 2 + 1][0] = rh[2]; Bf[np * 2 + 1][1] = rh[3];
                }
            }
#pragma unroll
            for (int mi = 0; mi < 2; mi++)
#pragma unroll
                for (int ni = 0; ni < 8; ni++) {
                    mma_f16(acc[mi][ni], Ah[mi], Bf[ni]);
                    mma_f16(acc[mi][ni], Al[mi], Bf[ni]);
                }
        }
        __syncthreads();
        st++; if (st >= NSTAGE) st = 0;
    }

    // ---- epilogue
    const int g = lane >> 2, t = lane & 3;
#pragma unroll
    for (int mi = 0; mi < 2; mi++) {
        int r0 = blockM + wm * 32 + mi * 16 + g;
#pragma unroll
        for (int ni = 0; ni < 8; ni++) {
            int c0 = blockN + wn * 64 + ni * 8 + 2 * t;
            if (c0 >= N) continue;
            bool c1ok = (c0 + 1) < N;
            float bv0 = bias ? bias[c0] : 0.0f;
            float bv1 = (bias && c1ok) ? bias[c0 + 1] : 0.0f;
            if (r0 < M) {
                float v0 = acc[mi][ni][0] + bv0;
                if (bias) v0 = v0 > 0.f ? v0 : 0.f;
                C[(size_t)r0 * N + c0] = v0;
                if (c1ok) {
                    float v1 = acc[mi][ni][1] + bv1;
                    if (bias) v1 = v1 > 0.f ? v1 : 0.f;
                    C[(size_t)r0 * N + c0 + 1] = v1;
                }
            }
            if (r0 + 8 < M) {
                float v2 = acc[mi][ni][2] + bv0;
                if (bias) v2 = v2 > 0.f ? v2 : 0.f;
                C[(size_t)(r0 + 8) * N + c0] = v2;
                if (c1ok) {
                    float v3 = acc[mi][ni][3] + bv1;
                    if (bias) v3 = v3 > 0.f ? v3 : 0.f;
                    C[(size_t)(r0 + 8) * N + c0 + 1] = v3;
                }
            }
        }
    }
}

// ---------------- orchestration ---------------------------------------------
extern "C" void kernel_launch(void* const* d_in, const int* in_sizes, int n_in,
                              void* d_out, int out_size) {
    const float* x  = (const float*)d_in[0];
    const void*  ei = d_in[1];
    const float* w1 = (const float*)d_in[2];
    const float* b1 = (const float*)d_in[3];
    const float* w2 = (const float*)d_in[4];
    const float* b2 = (const float*)d_in[5];
    const float* w3 = (const float*)d_in[6];
    const float* b3 = (const float*)d_in[7];
    float* out = (float*)d_out;
    int E = in_sizes[1] / 2;

    cudaFuncSetAttribute(k_mmagemm, cudaFuncAttributeMaxDynamicSharedMemorySize,
                         SMEM_TOTAL);

    int nb = (NN + 255) / 256;
    int eb = (E + 255) / 256;
    int spb = (NN * 32 + 255) / 256;
    int mt = (NN + TBM - 1) / TBM;   // 391

    // (1) layer-1 A convert    (2) layer-1 W convert
    k_cvtA1<<<(unsigned)(((long long)NN * 512 + 255) / 256), 256>>>(x);
    k_cvtW1<<<(unsigned)((768LL * 512 + 255) / 256), 256>>>(w1);
    // (3) detect + zero degree
    k_dzero<<<nb, 256>>>((const int*)ei);
    // (4) layer-1 GEMM: U = x @ [W0-W2 | W1 | W2]^T  -> g_u [NN,768]
    {
        dim3 g(768 / TBN, mt);
        k_mmagemm<<<g, 256, SMEM_TOTAL>>>(nullptr, nullptr, 5, NN, 768, 512);
    }
    // (5..9) graph prep + layer-2 gap zeroing + u2 fp16 stash
    k_count<<<eb, 256>>>(ei, E);
    k_dsc<<<1, 1024>>>();
    k_fill<<<eb, 256>>>(ei, E);
    k_zp2<<<(unsigned)(((long long)NN * 18 + 255) / 256), 256>>>();
    k_cvtU<<<(unsigned)(((long long)NN * 250 + 255) / 256), 256>>>();

    // (10) v = u1 + 2*Lhat(u2)  -> tx1 (str 250) + v-hi stash @SB_V
    k_spmmh<250><<<spb, 256>>>(SB_U2, 256, nullptr, 5, 512, 768, 5, 256, 768,
                               1, 250, 2.0f, 1.0f, nullptr, 0,
                               0, 0, SB_V, 256);
    // (11) h1 = relu(u0 + Lhat(v) + b1) -> h1 + A2-block0 (hi doubles as mirror)
    k_spmmh<250><<<spb, 256>>>(SB_V, 256, nullptr, 1, 0, 250, 5, 0, 768,
                               3, 250, 1.0f, 1.0f, b1, 1,
                               0, 768, 0, 0);
    // (12) tx1 = Lhat(h1) -> tx1 + A2-block1 @252
    k_spmmh<250><<<spb, 256>>>(0, 768, nullptr, 3, 0, 250, 3, 0, 250,
                               1, 250, 1.0f, 0.0f, nullptr, 0,
                               252, 768, 0, 0);
    // (13) tx2 = 2*Lhat(tx1) - h1 -> tx2 + A2-block2 @504
    k_spmmh<250><<<spb, 256>>>(252, 768, nullptr, 1, 0, 250, 3, 0, 250,
                               2, 250, 2.0f, -1.0f, nullptr, 0,
                               504, 768, 0, 0);
    // (14) layer-2 W convert, (15) layer-2 GEMM -> h2 [NN,500]
    k_cvtW2<<<(unsigned)((512LL * 768 + 255) / 256), 256>>>(w2);
    {
        dim3 g(512 / TBN, mt);
        k_mmagemm<<<g, 256, SMEM_TOTAL>>>(b2, nullptr, 4, NN, 500, 768);
    }
    // (16) layer-3 pad zeroing, (17) h2 -> A3-block0 (hi/lo)
    k_zp3<<<(unsigned)(((long long)NN * 36 + 255) / 256), 256>>>();
    k_cvtA3<<<(unsigned)(((long long)NN * 500 + 255) / 256), 256>>>();
    // (18) tx1 = Lhat(h2) -> tx1 + A3-block1 @500
    k_spmmh<500><<<spb, 256>>>(0, 1536, nullptr, 4, 0, 500, 4, 0, 500,
                               1, 500, 1.0f, 0.0f, nullptr, 0,
                               500, 1536, 0, 0);
    // (19) tx2 = 2*Lhat(tx1) - h2 -> tx2 + A3-block2 @1000
    k_spmmh<500><<<spb, 256>>>(500, 1536, nullptr, 1, 0, 500, 4, 0, 500,
                               2, 500, 2.0f, -1.0f, nullptr, 0,
                               1000, 1536, 0, 0);
    // (20) layer-3 W convert, (21) layer-3 GEMM -> out
    {
        long long tW = 1024LL * 1536;
        k_cvtW<<<(unsigned)((tW + 255) / 256), 256>>>(w3, 500, 1000, 1024, 1536);
        dim3 g(1024 / TBN, mt);
        k_mmagemm<<<g, 256, SMEM_TOTAL>>>(b3, out, 0, NN, 1000, 1536);
    }
}